// round 9
// baseline (speedup 1.0000x reference)
#include <cuda_runtime.h>
#include <cuda_bf16.h>
#include <math.h>
#include <stdint.h>

// ---------------- problem constants ----------------
#define DIMX   2048
#define NH     16
#define QLORA  1536
#define KVLORA 512
#define ROPE_D 64
#define QK_NOPE 128
#define QK_HEAD 192     // 128 + 64
#define V_HEAD 128
#define BSZ    2
#define SEQ    2048
#define NTOK   (BSZ*SEQ)        // 4096
#define KEFF   (KVLORA+ROPE_D)  // 576
#define EPSF   1e-6f

#define NEG_INF __int_as_float(0xff800000)

// ---------------- scratch (static device arrays; no cudaMalloc allowed) ----
__device__ float g_qa  [(size_t)NTOK * QLORA];
__device__ float g_q   [(size_t)NTOK * NH * QK_HEAD];
__device__ float g_kv  [(size_t)NTOK * KEFF];             // kvc 512 | k_pe 64
__device__ float g_qeff[(size_t)BSZ * NH * SEQ * KEFF];   // absorbed q 512 | roped q_pe 64
__device__ float g_scr [(size_t)BSZ * NH * SEQ * SEQ];    // scores / attn
__device__ float g_ao  [(size_t)BSZ * NH * SEQ * KVLORA];
__device__ float g_ov  [(size_t)NTOK * NH * V_HEAD];
__device__ float g_wnt [(size_t)NH * KVLORA * QK_NOPE];   // wkv_b_nope^T per head [c][d]
__device__ float g_kvt [(size_t)BSZ * KVLORA * SEQ];      // kvc^T per batch [c][t]

// ---------------- batch offset map: off = (z/div)*s1 + (z%mod)*s2 ----------
struct BMap { int div; long long s1; int mod; long long s2; };
__device__ __forceinline__ long long boff(const BMap m, int z) {
    return (long long)(z / m.div) * m.s1 + (long long)(z % m.mod) * m.s2;
}

// ---------------- bf16 split helpers ----------------
// v = hi + lo with hi, lo bf16; pack pairs (even k in low half)
__device__ __forceinline__ void split2(float x, float y, uint32_t& hi, uint32_t& lo) {
    __nv_bfloat16 hx = __float2bfloat16_rn(x);
    __nv_bfloat16 hy = __float2bfloat16_rn(y);
    __nv_bfloat16 lx = __float2bfloat16_rn(x - __bfloat162float(hx));
    __nv_bfloat16 ly = __float2bfloat16_rn(y - __bfloat162float(hy));
    hi = (uint32_t)__bfloat16_as_ushort(hx) | ((uint32_t)__bfloat16_as_ushort(hy) << 16);
    lo = (uint32_t)__bfloat16_as_ushort(lx) | ((uint32_t)__bfloat16_as_ushort(ly) << 16);
}

// mma.sync m16n8k16 bf16, fp32 accumulate
#define MMABF(d, a, b) \
    asm volatile("mma.sync.aligned.m16n8k16.row.col.f32.bf16.bf16.f32 " \
        "{%0,%1,%2,%3}, {%4,%5,%6,%7}, {%8,%9}, {%0,%1,%2,%3};" \
        : "+f"((d)[0]), "+f"((d)[1]), "+f"((d)[2]), "+f"((d)[3]) \
        : "r"((a)[0]), "r"((a)[1]), "r"((a)[2]), "r"((a)[3]), \
          "r"((b)[0]), "r"((b)[1]))

// ---------------- split-bf16 batched TN GEMM (near-fp32 precision) ---------
// C[m,n] = alpha * sum_k A[m,k] * B[n,k]  (+bias[n])
// A: [M,K] lda;  B: [N,K] ldb; fp32 K-major.
// Requirements: M % 128 == 0, K % 16 == 0, N % 4 == 0.
// trik: 0 = none, 1 = causal (skip tiles with n0 >= m0+128; softmax masks rest),
//       2 = k-limit (A[m,k]==0 for k>m => Kend = m0+128)
#define GBM 128
#define GBN 128
#define GBK 16
#define PBW 12   // smem words (b32) per 16-element bf16 row (24 bf16 = 16 + 8 pad)

__global__ void __launch_bounds__(256)
mma_gemm(float* __restrict__ Cb, const float* __restrict__ Ab,
         const float* __restrict__ Bb, const float* __restrict__ bias,
         float alpha, int trik, int M, int N, int K,
         int lda, int ldb, int ldc, BMap am, BMap bm, BMap cm)
{
    const int z = blockIdx.z;
    const int m0 = blockIdx.y * GBM;
    const int n0 = blockIdx.x * GBN;
    if (trik == 1 && n0 >= m0 + GBM) return;   // fully masked tile

    __shared__ uint32_t sA[2][GBM * PBW];      // [plane hi/lo][row*12 + word]
    __shared__ uint32_t sB[2][GBN * PBW];

    const float* A = Ab + boff(am, z);
    const float* B = Bb + boff(bm, z);
    float*       C = Cb + boff(cm, z);

    const int tid  = threadIdx.x;
    const int wid  = tid >> 5;
    const int lane = tid & 31;
    const int wm   = wid & 1;          // 2 warps in m
    const int wn   = wid >> 1;         // 4 warps in n
    const int g    = lane >> 2;        // group id (0..7)
    const int c    = lane & 3;         // thread in group (0..3)

    int Kend = K;
    if (trik == 2) { int lim = m0 + GBM; Kend = (lim < K) ? lim : K; }

    float acc[4][4][4];
    #pragma unroll
    for (int i = 0; i < 4; i++)
        #pragma unroll
        for (int j = 0; j < 4; j++)
            #pragma unroll
            for (int l = 0; l < 4; l++) acc[i][j][l] = 0.f;

    // per-thread load slots: chunks tid and tid+256 of 512 (row = chunk>>2, q = chunk&3)
    float4 ra[2], rb[2];
    const int row_[2] = { tid >> 2, (tid + 256) >> 2 };
    const int q_[2]   = { tid & 3, (tid + 256) & 3 };

    auto prefetch = [&](int k0) {
        #pragma unroll
        for (int i = 0; i < 2; i++) {
            int row = row_[i], q = q_[i];
            ra[i] = *reinterpret_cast<const float4*>(&A[(size_t)(m0 + row) * lda + k0 + q * 4]);
            if (n0 + row < N)
                rb[i] = *reinterpret_cast<const float4*>(&B[(size_t)(n0 + row) * ldb + k0 + q * 4]);
            else
                rb[i] = make_float4(0.f, 0.f, 0.f, 0.f);
        }
    };
    auto stores = [&]() {
        #pragma unroll
        for (int i = 0; i < 2; i++) {
            int w = row_[i] * PBW + q_[i] * 2;
            uint32_t h0, l0, h1, l1;
            split2(ra[i].x, ra[i].y, h0, l0);
            split2(ra[i].z, ra[i].w, h1, l1);
            sA[0][w] = h0; sA[0][w + 1] = h1;
            sA[1][w] = l0; sA[1][w + 1] = l1;
            split2(rb[i].x, rb[i].y, h0, l0);
            split2(rb[i].z, rb[i].w, h1, l1);
            sB[0][w] = h0; sB[0][w + 1] = h1;
            sB[1][w] = l0; sB[1][w + 1] = l1;
        }
    };

    prefetch(0);
    for (int k0 = 0; k0 < Kend; k0 += GBK) {
        stores();
        if (k0 + GBK < Kend) prefetch(k0 + GBK);
        __syncthreads();

        uint32_t ah[4][4], al[4][4], bh[4][2], bl[4][2];
        #pragma unroll
        for (int mt = 0; mt < 4; mt++) {
            int r0 = (wm * 64 + mt * 16 + g) * PBW;
            ah[mt][0] = sA[0][r0 + c];          al[mt][0] = sA[1][r0 + c];
            ah[mt][1] = sA[0][r0 + 96 + c];     al[mt][1] = sA[1][r0 + 96 + c];
            ah[mt][2] = sA[0][r0 + c + 4];      al[mt][2] = sA[1][r0 + c + 4];
            ah[mt][3] = sA[0][r0 + 96 + c + 4]; al[mt][3] = sA[1][r0 + 96 + c + 4];
        }
        #pragma unroll
        for (int nt = 0; nt < 4; nt++) {
            int r0 = (wn * 32 + nt * 8 + g) * PBW;
            bh[nt][0] = sB[0][r0 + c];     bl[nt][0] = sB[1][r0 + c];
            bh[nt][1] = sB[0][r0 + c + 4]; bl[nt][1] = sB[1][r0 + c + 4];
        }
        // pass 1: hi*hi; pass 2: hi*lo; pass 3: lo*hi (16-MMA dependency distance)
        #pragma unroll
        for (int mt = 0; mt < 4; mt++)
            #pragma unroll
            for (int nt = 0; nt < 4; nt++)
                MMABF(acc[mt][nt], ah[mt], bh[nt]);
        #pragma unroll
        for (int mt = 0; mt < 4; mt++)
            #pragma unroll
            for (int nt = 0; nt < 4; nt++)
                MMABF(acc[mt][nt], ah[mt], bl[nt]);
        #pragma unroll
        for (int mt = 0; mt < 4; mt++)
            #pragma unroll
            for (int nt = 0; nt < 4; nt++)
                MMABF(acc[mt][nt], al[mt], bh[nt]);
        __syncthreads();
    }

    // epilogue
    #pragma unroll
    for (int mt = 0; mt < 4; mt++) {
        int m = m0 + wm * 64 + mt * 16 + g;
        #pragma unroll
        for (int nt = 0; nt < 4; nt++) {
            int n = n0 + wn * 32 + nt * 8 + 2 * c;
            if (n >= N) continue;
            float b0 = 0.f, b1 = 0.f;
            if (bias) { b0 = bias[n]; b1 = bias[n + 1]; }
            float2 v0, v1;
            v0.x = acc[mt][nt][0] * alpha + b0;
            v0.y = acc[mt][nt][1] * alpha + b1;
            v1.x = acc[mt][nt][2] * alpha + b0;
            v1.y = acc[mt][nt][3] * alpha + b1;
            *reinterpret_cast<float2*>(&C[(size_t)m * ldc + n]) = v0;
            *reinterpret_cast<float2*>(&C[(size_t)(m + 8) * ldc + n]) = v1;
        }
    }
}

// ---------------- transposes ----------------
// wnt[h][c][d] = wkv_b[h][d][c]   (d < 128, c < 512; wkv_b row block = 256 rows)
__global__ void wnt_kernel(const float* __restrict__ w, float* __restrict__ wt) {
    __shared__ float t[32][33];
    int h = blockIdx.z;
    int c0 = blockIdx.x * 32, d0 = blockIdx.y * 32;
    int tx = threadIdx.x, ty = threadIdx.y;
    const float* src = w + (size_t)h * 256 * KVLORA;
    #pragma unroll
    for (int i = 0; i < 32; i += 8)
        t[ty + i][tx] = src[(size_t)(d0 + ty + i) * KVLORA + c0 + tx];
    __syncthreads();
    float* dst = wt + (size_t)h * KVLORA * QK_NOPE;
    #pragma unroll
    for (int i = 0; i < 32; i += 8)
        dst[(size_t)(c0 + ty + i) * QK_NOPE + d0 + tx] = t[tx][ty + i];
}

// kvt[b][c][t] = kv[b*SEQ + t][c]   (c < 512)
__global__ void kvt_kernel(const float* __restrict__ kv, float* __restrict__ kvt) {
    __shared__ float t[32][33];
    int b = blockIdx.z;
    int t0 = blockIdx.x * 32, c0 = blockIdx.y * 32;
    int tx = threadIdx.x, ty = threadIdx.y;
    const float* src = kv + (size_t)b * SEQ * KEFF;
    #pragma unroll
    for (int i = 0; i < 32; i += 8)
        t[ty + i][tx] = src[(size_t)(t0 + ty + i) * KEFF + c0 + tx];
    __syncthreads();
    float* dst = kvt + (size_t)b * KVLORA * SEQ;
    #pragma unroll
    for (int i = 0; i < 32; i += 8)
        dst[(size_t)(c0 + ty + i) * SEQ + t0 + tx] = t[tx][ty + i];
}

// ---------------- block reductions ----------------
__device__ __forceinline__ float block_reduce_sum(float v) {
    __shared__ float sh[32];
    int lane = threadIdx.x & 31, w = threadIdx.x >> 5;
    __syncthreads();
    #pragma unroll
    for (int o = 16; o; o >>= 1) v += __shfl_down_sync(0xffffffffu, v, o);
    if (lane == 0) sh[w] = v;
    __syncthreads();
    int nw = blockDim.x >> 5;
    v = (threadIdx.x < (unsigned)nw) ? sh[threadIdx.x] : 0.f;
    if (w == 0) {
        #pragma unroll
        for (int o = 16; o; o >>= 1) v += __shfl_down_sync(0xffffffffu, v, o);
        if (lane == 0) sh[0] = v;
    }
    __syncthreads();
    return sh[0];
}
__device__ __forceinline__ float block_reduce_max(float v) {
    __shared__ float sh[32];
    int lane = threadIdx.x & 31, w = threadIdx.x >> 5;
    __syncthreads();
    #pragma unroll
    for (int o = 16; o; o >>= 1) v = fmaxf(v, __shfl_down_sync(0xffffffffu, v, o));
    if (lane == 0) sh[w] = v;
    __syncthreads();
    int nw = blockDim.x >> 5;
    v = (threadIdx.x < (unsigned)nw) ? sh[threadIdx.x] : NEG_INF;
    if (w == 0) {
        #pragma unroll
        for (int o = 16; o; o >>= 1) v = fmaxf(v, __shfl_down_sync(0xffffffffu, v, o));
        if (lane == 0) sh[0] = v;
    }
    __syncthreads();
    return sh[0];
}

// ---------------- rmsnorm over a row of length n (in place) ----------------
__global__ void rmsnorm_kernel(float* __restrict__ x, const float* __restrict__ w, int n) {
    float* p = x + (long long)blockIdx.x * n;
    float ss = 0.f;
    for (int i = threadIdx.x; i < n; i += blockDim.x) { float v = p[i]; ss += v * v; }
    float tot = block_reduce_sum(ss);
    float scale = rsqrtf(tot / (float)n + EPSF);
    for (int i = threadIdx.x; i < n; i += blockDim.x) p[i] = p[i] * scale * w[i];
}

// ---------------- kv post: rmsnorm first 512, rope last 64 (in place) ------
__global__ void kv_post_kernel(float* __restrict__ kv, const float* __restrict__ w,
                               const float* __restrict__ freqs) {
    int t = blockIdx.x;
    int s = t % SEQ;
    float* p = kv + (long long)t * KEFF;
    float ss = 0.f;
    for (int i = threadIdx.x; i < KVLORA; i += blockDim.x) { float v = p[i]; ss += v * v; }
    float tot = block_reduce_sum(ss);
    float scale = rsqrtf(tot / (float)KVLORA + EPSF);
    for (int i = threadIdx.x; i < KVLORA; i += blockDim.x) p[i] = p[i] * scale * w[i];
    if (threadIdx.x < ROPE_D / 2) {
        int i = threadIdx.x;
        float c  = freqs[s * ROPE_D + 2 * i];
        float sn = freqs[s * ROPE_D + 2 * i + 1];
        float x0 = p[KVLORA + 2 * i], x1 = p[KVLORA + 2 * i + 1];
        p[KVLORA + 2 * i]     = x0 * c - x1 * sn;
        p[KVLORA + 2 * i + 1] = x1 * c + x0 * sn;
    }
}

// ---------------- rope q_pe -> qeff[..., 512:576] ----------------
__global__ void qrope_kernel(const float* __restrict__ q, float* __restrict__ qeff,
                             const float* __restrict__ freqs) {
    int t = blockIdx.x;
    int b = t / SEQ, s = t % SEQ;
    int h = threadIdx.x >> 5;
    int i = threadIdx.x & 31;
    float c  = freqs[s * ROPE_D + 2 * i];
    float sn = freqs[s * ROPE_D + 2 * i + 1];
    const float* qp = q + (long long)t * NH * QK_HEAD + h * QK_HEAD + QK_NOPE;
    float x0 = qp[2 * i], x1 = qp[2 * i + 1];
    float* o = qeff + ((long long)(b * NH + h) * SEQ + s) * KEFF + KVLORA;
    o[2 * i]     = x0 * c - x1 * sn;
    o[2 * i + 1] = x1 * c + x0 * sn;
}

// ---------------- causal row softmax (valid length s+1; zero above) --------
__global__ void softmax_kernel(float* __restrict__ S) {
    const int n = SEQ;
    int s = blockIdx.x % SEQ;       // row position within its (b,h) matrix
    float* p = S + (long long)blockIdx.x * n;
    float e[8];
    float mx = NEG_INF;
    #pragma unroll
    for (int k = 0; k < 8; k++) {
        int idx = threadIdx.x + k * 256;
        e[k] = (idx <= s) ? p[idx] : NEG_INF;
        mx = fmaxf(mx, e[k]);
    }
    mx = block_reduce_max(mx);
    float sum = 0.f;
    #pragma unroll
    for (int k = 0; k < 8; k++) {
        e[k] = expf(e[k] - mx);     // exp(-inf) = 0 for masked entries
        sum += e[k];
    }
    sum = block_reduce_sum(sum);
    float inv = 1.f / sum;
    #pragma unroll
    for (int k = 0; k < 8; k++) {
        int idx = threadIdx.x + k * 256;
        p[idx] = (idx <= s) ? e[k] * inv : 0.f;
    }
}

// ---------------- launch ----------------
extern "C" void kernel_launch(void* const* d_in, const int* in_sizes, int n_in,
                              void* d_out, int out_size) {
    int pbase = (n_in > 3 && in_sizes[3] == 1) ? 4 : 3;
    const float* x         = (const float*)d_in[0];
    const float* freqs     = (const float*)d_in[1];
    const float* wq_a_w    = (const float*)d_in[pbase + 0];
    const float* wq_a_b    = (const float*)d_in[pbase + 1];
    const float* q_norm_w  = (const float*)d_in[pbase + 2];
    const float* wq_b_w    = (const float*)d_in[pbase + 3];
    const float* wq_b_b    = (const float*)d_in[pbase + 4];
    const float* wkv_a_w   = (const float*)d_in[pbase + 5];
    const float* wkv_a_b   = (const float*)d_in[pbase + 6];
    const float* kv_norm_w = (const float*)d_in[pbase + 7];
    const float* wkv_b_w   = (const float*)d_in[pbase + 8];
    const float* wo_w      = (const float*)d_in[pbase + 9];
    const float* wo_b      = (const float*)d_in[pbase + 10];
    float* out = (float*)d_out;

    float *qa, *q, *kv, *qeff, *scr, *ao, *ov, *wnt, *kvt;
    cudaGetSymbolAddress((void**)&qa,   g_qa);
    cudaGetSymbolAddress((void**)&q,    g_q);
    cudaGetSymbolAddress((void**)&kv,   g_kv);
    cudaGetSymbolAddress((void**)&qeff, g_qeff);
    cudaGetSymbolAddress((void**)&scr,  g_scr);
    cudaGetSymbolAddress((void**)&ao,   g_ao);
    cudaGetSymbolAddress((void**)&ov,   g_ov);
    cudaGetSymbolAddress((void**)&wnt,  g_wnt);
    cudaGetSymbolAddress((void**)&kvt,  g_kvt);

    const BMap id = {1, 0, 1, 0};
    const dim3 blk(256);

    // 0) transpose wkv_b nope blocks: wnt[h][c][d]
    wnt_kernel<<<dim3(KVLORA / 32, QK_NOPE / 32, NH), dim3(32, 8)>>>(wkv_b_w, wnt);

    // 1) qa = x @ wq_a_w^T + b
    mma_gemm<<<dim3(12, 32, 1), blk>>>(qa, x, wq_a_w, wq_a_b, 1.f, 0,
        NTOK, QLORA, DIMX, DIMX, DIMX, QLORA, id, id, id);

    // 2) rmsnorm(qa)
    rmsnorm_kernel<<<NTOK, 256>>>(qa, q_norm_w, QLORA);

    // 3) q = qa @ wq_b_w^T + b
    mma_gemm<<<dim3(24, 32, 1), blk>>>(q, qa, wq_b_w, wq_b_b, 1.f, 0,
        NTOK, NH * QK_HEAD, QLORA, QLORA, QLORA, NH * QK_HEAD, id, id, id);

    // 4) kv = x @ wkv_a_w^T + b
    mma_gemm<<<dim3(5, 32, 1), blk>>>(kv, x, wkv_a_w, wkv_a_b, 1.f, 0,
        NTOK, KEFF, DIMX, DIMX, DIMX, KEFF, id, id, id);

    // 5) kvc = rmsnorm(kv[:,:512]); k_pe = rope(kv[:,512:])
    kv_post_kernel<<<NTOK, 256>>>(kv, kv_norm_w, freqs);

    // 5b) kvt[b][c][t] = kvc^T
    kvt_kernel<<<dim3(SEQ / 32, KVLORA / 32, BSZ), dim3(32, 8)>>>(kv, kvt);

    // 6) qeff[...,512:576] = rope(q_pe)
    qrope_kernel<<<NTOK, 512>>>(q, qeff, freqs);

    // 7) qeff[z,:, :512] = q_nope @ wnt[h]^T    (TN: B = wnt[h] [512,128])
    {
        BMap am = {NH, (long long)SEQ * NH * QK_HEAD, NH, QK_HEAD};
        BMap bm = {1, 0, NH, (long long)KVLORA * QK_NOPE};
        BMap cm = {1, (long long)SEQ * KEFF, 1, 0};
        mma_gemm<<<dim3(4, 16, 32), blk>>>(qeff, q, wnt, nullptr, 1.f, 0,
            SEQ, KVLORA, QK_NOPE, NH * QK_HEAD, QK_NOPE, KEFF, am, bm, cm);
    }

    // 8) scores = scale * Qeff @ Keff^T, causal (TN: B = kv rows [t,576])
    {
        BMap am = {1, (long long)SEQ * KEFF, 1, 0};
        BMap bm = {NH, (long long)SEQ * KEFF, 1, 0};
        BMap cm = {1, (long long)SEQ * SEQ, 1, 0};
        const float scale = 0.07216878364870323f;    // 192^-0.5
        mma_gemm<<<dim3(16, 16, 32), blk>>>(scr, qeff, kv, nullptr, scale, 1,
            SEQ, SEQ, KEFF, KEFF, KEFF, SEQ, am, bm, cm);
    }

    // 9) causal softmax rows
    softmax_kernel<<<BSZ * NH * SEQ, 256>>>(scr);

    // 10) ao = attn @ kvc   (TN: B = kvt[b] [512, 2048], k-limited)
    {
        BMap am = {1, (long long)SEQ * SEQ, 1, 0};
        BMap bm = {NH, (long long)KVLORA * SEQ, 1, 0};
        BMap cm = {1, (long long)SEQ * KVLORA, 1, 0};
        mma_gemm<<<dim3(4, 16, 32), blk>>>(ao, scr, kvt, nullptr, 1.f, 2,
            SEQ, KVLORA, SEQ, SEQ, SEQ, KVLORA, am, bm, cm);
    }

    // 11) ov = ao @ wv^T  (TN: B = wkv_b[h][128:256,:] rows [d,512])
    {
        BMap am = {1, (long long)SEQ * KVLORA, 1, 0};
        BMap bm = {1, 0, NH, (long long)256 * KVLORA};
        BMap cm = {NH, (long long)SEQ * NH * V_HEAD, NH, V_HEAD};
        mma_gemm<<<dim3(1, 16, 32), blk>>>(ov, ao, wkv_b_w + (long long)QK_NOPE * KVLORA,
            nullptr, 1.f, 0,
            SEQ, V_HEAD, KVLORA, KVLORA, KVLORA, NH * V_HEAD, am, bm, cm);
    }

    // 12) out = ov @ wo_w^T + wo_b
    mma_gemm<<<dim3(16, 32, 1), blk>>>(out, ov, wo_w, wo_b, 1.f, 0,
        NTOK, DIMX, NH * V_HEAD, NH * V_HEAD, NH * V_HEAD, DIMX, id, id, id);
}

// round 10
// speedup vs baseline: 1.0007x; 1.0007x over previous
#include <cuda_runtime.h>
#include <cuda_bf16.h>
#include <math.h>
#include <stdint.h>

// ---------------- problem constants ----------------
#define DIMX   2048
#define NH     16
#define QLORA  1536
#define KVLORA 512
#define ROPE_D 64
#define QK_NOPE 128
#define QK_HEAD 192     // 128 + 64
#define V_HEAD 128
#define BSZ    2
#define SEQ    2048
#define NTOK   (BSZ*SEQ)        // 4096
#define KEFF   (KVLORA+ROPE_D)  // 576
#define EPSF   1e-6f

#define NEG_INF __int_as_float(0xff800000)

// ---------------- scratch (static device arrays; no cudaMalloc allowed) ----
__device__ float g_qa  [(size_t)NTOK * QLORA];
__device__ float g_q   [(size_t)NTOK * NH * QK_HEAD];
__device__ float g_kv  [(size_t)NTOK * KEFF];             // kvc 512 | k_pe 64
__device__ float g_qeff[(size_t)BSZ * NH * SEQ * KEFF];   // absorbed q 512 | roped q_pe 64
__device__ float g_scr [(size_t)BSZ * NH * SEQ * SEQ];    // scores / attn
__device__ float g_ao  [(size_t)BSZ * NH * SEQ * KVLORA];
__device__ float g_ov  [(size_t)NTOK * NH * V_HEAD];
__device__ float g_wnt [(size_t)NH * KVLORA * QK_NOPE];   // wkv_b_nope^T per head [c][d]
__device__ float g_kvt [(size_t)BSZ * KVLORA * SEQ];      // kvc^T per batch [c][t]

// ---------------- batch offset map: off = (z/div)*s1 + (z%mod)*s2 ----------
struct BMap { int div; long long s1; int mod; long long s2; };
__device__ __forceinline__ long long boff(const BMap m, int z) {
    return (long long)(z / m.div) * m.s1 + (long long)(z % m.mod) * m.s2;
}

// ---------------- bf16 split helpers ----------------
// v = hi + lo with hi, lo bf16; pack pairs (even k in low half)
__device__ __forceinline__ void split2(float x, float y, uint32_t& hi, uint32_t& lo) {
    __nv_bfloat16 hx = __float2bfloat16_rn(x);
    __nv_bfloat16 hy = __float2bfloat16_rn(y);
    __nv_bfloat16 lx = __float2bfloat16_rn(x - __bfloat162float(hx));
    __nv_bfloat16 ly = __float2bfloat16_rn(y - __bfloat162float(hy));
    hi = (uint32_t)__bfloat16_as_ushort(hx) | ((uint32_t)__bfloat16_as_ushort(hy) << 16);
    lo = (uint32_t)__bfloat16_as_ushort(lx) | ((uint32_t)__bfloat16_as_ushort(ly) << 16);
}

// mma.sync m16n8k16 bf16, fp32 accumulate
#define MMABF(d, a, b) \
    asm volatile("mma.sync.aligned.m16n8k16.row.col.f32.bf16.bf16.f32 " \
        "{%0,%1,%2,%3}, {%4,%5,%6,%7}, {%8,%9}, {%0,%1,%2,%3};" \
        : "+f"((d)[0]), "+f"((d)[1]), "+f"((d)[2]), "+f"((d)[3]) \
        : "r"((a)[0]), "r"((a)[1]), "r"((a)[2]), "r"((a)[3]), \
          "r"((b)[0]), "r"((b)[1]))

// ---------------- split-bf16 batched TN GEMM (near-fp32 precision) ---------
// C[m,n] = alpha * sum_k A[m,k] * B[n,k]  (+bias[n])
// A: [M,K] lda;  B: [N,K] ldb; fp32 K-major.
// Requirements: M % 128 == 0, K % 16 == 0, N % 4 == 0.
// trik: 0 = none, 1 = causal (skip tiles with n0 >= m0+128; softmax masks rest),
//       2 = k-limit (A[m,k]==0 for k>m => Kend = m0+128)
#define GBM 128
#define GBN 128
#define GBK 16
#define PBW 12   // smem words (b32) per 16-element bf16 row (24 bf16 = 16 + 8 pad)

__global__ void __launch_bounds__(256)
mma_gemm(float* __restrict__ Cb, const float* __restrict__ Ab,
         const float* __restrict__ Bb, const float* __restrict__ bias,
         float alpha, int trik, int M, int N, int K,
         int lda, int ldb, int ldc, BMap am, BMap bm, BMap cm)
{
    const int z = blockIdx.z;
    const int m0 = blockIdx.y * GBM;
    const int n0 = blockIdx.x * GBN;
    if (trik == 1 && n0 >= m0 + GBM) return;   // fully masked tile

    __shared__ uint32_t sA[2][GBM * PBW];      // [plane hi/lo][row*12 + word]
    __shared__ uint32_t sB[2][GBN * PBW];

    const float* A = Ab + boff(am, z);
    const float* B = Bb + boff(bm, z);
    float*       C = Cb + boff(cm, z);

    const int tid  = threadIdx.x;
    const int wid  = tid >> 5;
    const int lane = tid & 31;
    const int wm   = wid & 1;          // 2 warps in m
    const int wn   = wid >> 1;         // 4 warps in n
    const int g    = lane >> 2;        // group id (0..7)
    const int c    = lane & 3;         // thread in group (0..3)

    int Kend = K;
    if (trik == 2) { int lim = m0 + GBM; Kend = (lim < K) ? lim : K; }

    float acc[4][4][4];
    #pragma unroll
    for (int i = 0; i < 4; i++)
        #pragma unroll
        for (int j = 0; j < 4; j++)
            #pragma unroll
            for (int l = 0; l < 4; l++) acc[i][j][l] = 0.f;

    // per-thread load slots: chunks tid and tid+256 of 512 (row = chunk>>2, q = chunk&3)
    float4 ra[2], rb[2];
    const int row_[2] = { tid >> 2, (tid + 256) >> 2 };
    const int q_[2]   = { tid & 3, (tid + 256) & 3 };

    auto prefetch = [&](int k0) {
        #pragma unroll
        for (int i = 0; i < 2; i++) {
            int row = row_[i], q = q_[i];
            ra[i] = *reinterpret_cast<const float4*>(&A[(size_t)(m0 + row) * lda + k0 + q * 4]);
            if (n0 + row < N)
                rb[i] = *reinterpret_cast<const float4*>(&B[(size_t)(n0 + row) * ldb + k0 + q * 4]);
            else
                rb[i] = make_float4(0.f, 0.f, 0.f, 0.f);
        }
    };
    auto stores = [&]() {
        #pragma unroll
        for (int i = 0; i < 2; i++) {
            int w = row_[i] * PBW + q_[i] * 2;
            uint32_t h0, l0, h1, l1;
            split2(ra[i].x, ra[i].y, h0, l0);
            split2(ra[i].z, ra[i].w, h1, l1);
            sA[0][w] = h0; sA[0][w + 1] = h1;
            sA[1][w] = l0; sA[1][w + 1] = l1;
            split2(rb[i].x, rb[i].y, h0, l0);
            split2(rb[i].z, rb[i].w, h1, l1);
            sB[0][w] = h0; sB[0][w + 1] = h1;
            sB[1][w] = l0; sB[1][w + 1] = l1;
        }
    };

    prefetch(0);
    for (int k0 = 0; k0 < Kend; k0 += GBK) {
        stores();
        if (k0 + GBK < Kend) prefetch(k0 + GBK);
        __syncthreads();

        uint32_t ah[4][4], al[4][4], bh[4][2], bl[4][2];
        #pragma unroll
        for (int mt = 0; mt < 4; mt++) {
            int r0 = (wm * 64 + mt * 16 + g) * PBW;
            ah[mt][0] = sA[0][r0 + c];          al[mt][0] = sA[1][r0 + c];
            ah[mt][1] = sA[0][r0 + 96 + c];     al[mt][1] = sA[1][r0 + 96 + c];
            ah[mt][2] = sA[0][r0 + c + 4];      al[mt][2] = sA[1][r0 + c + 4];
            ah[mt][3] = sA[0][r0 + 96 + c + 4]; al[mt][3] = sA[1][r0 + 96 + c + 4];
        }
        #pragma unroll
        for (int nt = 0; nt < 4; nt++) {
            int r0 = (wn * 32 + nt * 8 + g) * PBW;
            bh[nt][0] = sB[0][r0 + c];     bl[nt][0] = sB[1][r0 + c];
            bh[nt][1] = sB[0][r0 + c + 4]; bl[nt][1] = sB[1][r0 + c + 4];
        }
        // pass 1: hi*hi; pass 2: hi*lo; pass 3: lo*hi (16-MMA dependency distance)
        #pragma unroll
        for (int mt = 0; mt < 4; mt++)
            #pragma unroll
            for (int nt = 0; nt < 4; nt++)
                MMABF(acc[mt][nt], ah[mt], bh[nt]);
        #pragma unroll
        for (int mt = 0; mt < 4; mt++)
            #pragma unroll
            for (int nt = 0; nt < 4; nt++)
                MMABF(acc[mt][nt], ah[mt], bl[nt]);
        #pragma unroll
        for (int mt = 0; mt < 4; mt++)
            #pragma unroll
            for (int nt = 0; nt < 4; nt++)
                MMABF(acc[mt][nt], al[mt], bh[nt]);
        __syncthreads();
    }

    // epilogue
    #pragma unroll
    for (int mt = 0; mt < 4; mt++) {
        int m = m0 + wm * 64 + mt * 16 + g;
        #pragma unroll
        for (int nt = 0; nt < 4; nt++) {
            int n = n0 + wn * 32 + nt * 8 + 2 * c;
            if (n >= N) continue;
            float b0 = 0.f, b1 = 0.f;
            if (bias) { b0 = bias[n]; b1 = bias[n + 1]; }
            float2 v0, v1;
            v0.x = acc[mt][nt][0] * alpha + b0;
            v0.y = acc[mt][nt][1] * alpha + b1;
            v1.x = acc[mt][nt][2] * alpha + b0;
            v1.y = acc[mt][nt][3] * alpha + b1;
            *reinterpret_cast<float2*>(&C[(size_t)m * ldc + n]) = v0;
            *reinterpret_cast<float2*>(&C[(size_t)(m + 8) * ldc + n]) = v1;
        }
    }
}

// ---------------- transposes ----------------
// wnt[h][c][d] = wkv_b[h][d][c]   (d < 128, c < 512; wkv_b row block = 256 rows)
__global__ void wnt_kernel(const float* __restrict__ w, float* __restrict__ wt) {
    __shared__ float t[32][33];
    int h = blockIdx.z;
    int c0 = blockIdx.x * 32, d0 = blockIdx.y * 32;
    int tx = threadIdx.x, ty = threadIdx.y;
    const float* src = w + (size_t)h * 256 * KVLORA;
    #pragma unroll
    for (int i = 0; i < 32; i += 8)
        t[ty + i][tx] = src[(size_t)(d0 + ty + i) * KVLORA + c0 + tx];
    __syncthreads();
    float* dst = wt + (size_t)h * KVLORA * QK_NOPE;
    #pragma unroll
    for (int i = 0; i < 32; i += 8)
        dst[(size_t)(c0 + ty + i) * QK_NOPE + d0 + tx] = t[tx][ty + i];
}

// kvt[b][c][t] = kv[b*SEQ + t][c]   (c < 512)
__global__ void kvt_kernel(const float* __restrict__ kv, float* __restrict__ kvt) {
    __shared__ float t[32][33];
    int b = blockIdx.z;
    int t0 = blockIdx.x * 32, c0 = blockIdx.y * 32;
    int tx = threadIdx.x, ty = threadIdx.y;
    const float* src = kv + (size_t)b * SEQ * KEFF;
    #pragma unroll
    for (int i = 0; i < 32; i += 8)
        t[ty + i][tx] = src[(size_t)(t0 + ty + i) * KEFF + c0 + tx];
    __syncthreads();
    float* dst = kvt + (size_t)b * KVLORA * SEQ;
    #pragma unroll
    for (int i = 0; i < 32; i += 8)
        dst[(size_t)(c0 + ty + i) * SEQ + t0 + tx] = t[tx][ty + i];
}

// ---------------- block reductions ----------------
__device__ __forceinline__ float block_reduce_sum(float v) {
    __shared__ float sh[32];
    int lane = threadIdx.x & 31, w = threadIdx.x >> 5;
    __syncthreads();
    #pragma unroll
    for (int o = 16; o; o >>= 1) v += __shfl_down_sync(0xffffffffu, v, o);
    if (lane == 0) sh[w] = v;
    __syncthreads();
    int nw = blockDim.x >> 5;
    v = (threadIdx.x < (unsigned)nw) ? sh[threadIdx.x] : 0.f;
    if (w == 0) {
        #pragma unroll
        for (int o = 16; o; o >>= 1) v += __shfl_down_sync(0xffffffffu, v, o);
        if (lane == 0) sh[0] = v;
    }
    __syncthreads();
    return sh[0];
}
__device__ __forceinline__ float block_reduce_max(float v) {
    __shared__ float sh[32];
    int lane = threadIdx.x & 31, w = threadIdx.x >> 5;
    __syncthreads();
    #pragma unroll
    for (int o = 16; o; o >>= 1) v = fmaxf(v, __shfl_down_sync(0xffffffffu, v, o));
    if (lane == 0) sh[w] = v;
    __syncthreads();
    int nw = blockDim.x >> 5;
    v = (threadIdx.x < (unsigned)nw) ? sh[threadIdx.x] : NEG_INF;
    if (w == 0) {
        #pragma unroll
        for (int o = 16; o; o >>= 1) v = fmaxf(v, __shfl_down_sync(0xffffffffu, v, o));
        if (lane == 0) sh[0] = v;
    }
    __syncthreads();
    return sh[0];
}

// ---------------- rmsnorm over a row of length n (in place) ----------------
__global__ void rmsnorm_kernel(float* __restrict__ x, const float* __restrict__ w, int n) {
    float* p = x + (long long)blockIdx.x * n;
    float ss = 0.f;
    for (int i = threadIdx.x; i < n; i += blockDim.x) { float v = p[i]; ss += v * v; }
    float tot = block_reduce_sum(ss);
    float scale = rsqrtf(tot / (float)n + EPSF);
    for (int i = threadIdx.x; i < n; i += blockDim.x) p[i] = p[i] * scale * w[i];
}

// ---------------- kv post: rmsnorm first 512, rope last 64 (in place) ------
__global__ void kv_post_kernel(float* __restrict__ kv, const float* __restrict__ w,
                               const float* __restrict__ freqs) {
    int t = blockIdx.x;
    int s = t % SEQ;
    float* p = kv + (long long)t * KEFF;
    float ss = 0.f;
    for (int i = threadIdx.x; i < KVLORA; i += blockDim.x) { float v = p[i]; ss += v * v; }
    float tot = block_reduce_sum(ss);
    float scale = rsqrtf(tot / (float)KVLORA + EPSF);
    for (int i = threadIdx.x; i < KVLORA; i += blockDim.x) p[i] = p[i] * scale * w[i];
    if (threadIdx.x < ROPE_D / 2) {
        int i = threadIdx.x;
        float c  = freqs[s * ROPE_D + 2 * i];
        float sn = freqs[s * ROPE_D + 2 * i + 1];
        float x0 = p[KVLORA + 2 * i], x1 = p[KVLORA + 2 * i + 1];
        p[KVLORA + 2 * i]     = x0 * c - x1 * sn;
        p[KVLORA + 2 * i + 1] = x1 * c + x0 * sn;
    }
}

// ---------------- rope q_pe -> qeff[..., 512:576] ----------------
__global__ void qrope_kernel(const float* __restrict__ q, float* __restrict__ qeff,
                             const float* __restrict__ freqs) {
    int t = blockIdx.x;
    int b = t / SEQ, s = t % SEQ;
    int h = threadIdx.x >> 5;
    int i = threadIdx.x & 31;
    float c  = freqs[s * ROPE_D + 2 * i];
    float sn = freqs[s * ROPE_D + 2 * i + 1];
    const float* qp = q + (long long)t * NH * QK_HEAD + h * QK_HEAD + QK_NOPE;
    float x0 = qp[2 * i], x1 = qp[2 * i + 1];
    float* o = qeff + ((long long)(b * NH + h) * SEQ + s) * KEFF + KVLORA;
    o[2 * i]     = x0 * c - x1 * sn;
    o[2 * i + 1] = x1 * c + x0 * sn;
}

// ---------------- causal row softmax (valid length s+1; zero above) --------
__global__ void softmax_kernel(float* __restrict__ S) {
    const int n = SEQ;
    int s = blockIdx.x % SEQ;       // row position within its (b,h) matrix
    float* p = S + (long long)blockIdx.x * n;
    float e[8];
    float mx = NEG_INF;
    #pragma unroll
    for (int k = 0; k < 8; k++) {
        int idx = threadIdx.x + k * 256;
        e[k] = (idx <= s) ? p[idx] : NEG_INF;
        mx = fmaxf(mx, e[k]);
    }
    mx = block_reduce_max(mx);
    float sum = 0.f;
    #pragma unroll
    for (int k = 0; k < 8; k++) {
        e[k] = expf(e[k] - mx);     // exp(-inf) = 0 for masked entries
        sum += e[k];
    }
    sum = block_reduce_sum(sum);
    float inv = 1.f / sum;
    #pragma unroll
    for (int k = 0; k < 8; k++) {
        int idx = threadIdx.x + k * 256;
        p[idx] = (idx <= s) ? e[k] * inv : 0.f;
    }
}

// ---------------- launch ----------------
extern "C" void kernel_launch(void* const* d_in, const int* in_sizes, int n_in,
                              void* d_out, int out_size) {
    int pbase = (n_in > 3 && in_sizes[3] == 1) ? 4 : 3;
    const float* x         = (const float*)d_in[0];
    const float* freqs     = (const float*)d_in[1];
    const float* wq_a_w    = (const float*)d_in[pbase + 0];
    const float* wq_a_b    = (const float*)d_in[pbase + 1];
    const float* q_norm_w  = (const float*)d_in[pbase + 2];
    const float* wq_b_w    = (const float*)d_in[pbase + 3];
    const float* wq_b_b    = (const float*)d_in[pbase + 4];
    const float* wkv_a_w   = (const float*)d_in[pbase + 5];
    const float* wkv_a_b   = (const float*)d_in[pbase + 6];
    const float* kv_norm_w = (const float*)d_in[pbase + 7];
    const float* wkv_b_w   = (const float*)d_in[pbase + 8];
    const float* wo_w      = (const float*)d_in[pbase + 9];
    const float* wo_b      = (const float*)d_in[pbase + 10];
    float* out = (float*)d_out;

    float *qa, *q, *kv, *qeff, *scr, *ao, *ov, *wnt, *kvt;
    cudaGetSymbolAddress((void**)&qa,   g_qa);
    cudaGetSymbolAddress((void**)&q,    g_q);
    cudaGetSymbolAddress((void**)&kv,   g_kv);
    cudaGetSymbolAddress((void**)&qeff, g_qeff);
    cudaGetSymbolAddress((void**)&scr,  g_scr);
    cudaGetSymbolAddress((void**)&ao,   g_ao);
    cudaGetSymbolAddress((void**)&ov,   g_ov);
    cudaGetSymbolAddress((void**)&wnt,  g_wnt);
    cudaGetSymbolAddress((void**)&kvt,  g_kvt);

    const BMap id = {1, 0, 1, 0};
    const dim3 blk(256);

    // 0) transpose wkv_b nope blocks: wnt[h][c][d]
    wnt_kernel<<<dim3(KVLORA / 32, QK_NOPE / 32, NH), dim3(32, 8)>>>(wkv_b_w, wnt);

    // 1) qa = x @ wq_a_w^T + b
    mma_gemm<<<dim3(12, 32, 1), blk>>>(qa, x, wq_a_w, wq_a_b, 1.f, 0,
        NTOK, QLORA, DIMX, DIMX, DIMX, QLORA, id, id, id);

    // 2) rmsnorm(qa)
    rmsnorm_kernel<<<NTOK, 256>>>(qa, q_norm_w, QLORA);

    // 3) q = qa @ wq_b_w^T + b
    mma_gemm<<<dim3(24, 32, 1), blk>>>(q, qa, wq_b_w, wq_b_b, 1.f, 0,
        NTOK, NH * QK_HEAD, QLORA, QLORA, QLORA, NH * QK_HEAD, id, id, id);

    // 4) kv = x @ wkv_a_w^T + b
    mma_gemm<<<dim3(5, 32, 1), blk>>>(kv, x, wkv_a_w, wkv_a_b, 1.f, 0,
        NTOK, KEFF, DIMX, DIMX, DIMX, KEFF, id, id, id);

    // 5) kvc = rmsnorm(kv[:,:512]); k_pe = rope(kv[:,512:])
    kv_post_kernel<<<NTOK, 256>>>(kv, kv_norm_w, freqs);

    // 5b) kvt[b][c][t] = kvc^T
    kvt_kernel<<<dim3(SEQ / 32, KVLORA / 32, BSZ), dim3(32, 8)>>>(kv, kvt);

    // 6) qeff[...,512:576] = rope(q_pe)
    qrope_kernel<<<NTOK, 512>>>(q, qeff, freqs);

    // 7) qeff[z,:, :512] = q_nope @ wnt[h]^T    (TN: B = wnt[h] [512,128])
    {
        BMap am = {NH, (long long)SEQ * NH * QK_HEAD, NH, QK_HEAD};
        BMap bm = {1, 0, NH, (long long)KVLORA * QK_NOPE};
        BMap cm = {1, (long long)SEQ * KEFF, 1, 0};
        mma_gemm<<<dim3(4, 16, 32), blk>>>(qeff, q, wnt, nullptr, 1.f, 0,
            SEQ, KVLORA, QK_NOPE, NH * QK_HEAD, QK_NOPE, KEFF, am, bm, cm);
    }

    // 8) scores = scale * Qeff @ Keff^T, causal (TN: B = kv rows [t,576])
    {
        BMap am = {1, (long long)SEQ * KEFF, 1, 0};
        BMap bm = {NH, (long long)SEQ * KEFF, 1, 0};
        BMap cm = {1, (long long)SEQ * SEQ, 1, 0};
        const float scale = 0.07216878364870323f;    // 192^-0.5
        mma_gemm<<<dim3(16, 16, 32), blk>>>(scr, qeff, kv, nullptr, scale, 1,
            SEQ, SEQ, KEFF, KEFF, KEFF, SEQ, am, bm, cm);
    }

    // 9) causal softmax rows
    softmax_kernel<<<BSZ * NH * SEQ, 256>>>(scr);

    // 10) ao = attn @ kvc   (TN: B = kvt[b] [512, 2048], k-limited)
    {
        BMap am = {1, (long long)SEQ * SEQ, 1, 0};
        BMap bm = {NH, (long long)KVLORA * SEQ, 1, 0};
        BMap cm = {1, (long long)SEQ * KVLORA, 1, 0};
        mma_gemm<<<dim3(4, 16, 32), blk>>>(ao, scr, kvt, nullptr, 1.f, 2,
            SEQ, KVLORA, SEQ, SEQ, SEQ, KVLORA, am, bm, cm);
    }

    // 11) ov = ao @ wv^T  (TN: B = wkv_b[h][128:256,:] rows [d,512])
    {
        BMap am = {1, (long long)SEQ * KVLORA, 1, 0};
        BMap bm = {1, 0, NH, (long long)256 * KVLORA};
        BMap cm = {NH, (long long)SEQ * NH * V_HEAD, NH, V_HEAD};
        mma_gemm<<<dim3(1, 16, 32), blk>>>(ov, ao, wkv_b_w + (long long)QK_NOPE * KVLORA,
            nullptr, 1.f, 0,
            SEQ, V_HEAD, KVLORA, KVLORA, KVLORA, NH * V_HEAD, am, bm, cm);
    }

    // 12) out = ov @ wo_w^T + wo_b
    mma_gemm<<<dim3(16, 32, 1), blk>>>(out, ov, wo_w, wo_b, 1.f, 0,
        NTOK, DIMX, NH * V_HEAD, NH * V_HEAD, NH * V_HEAD, DIMX, id, id, id);
}

// round 11
// speedup vs baseline: 1.2471x; 1.2462x over previous
#include <cuda_runtime.h>
#include <cuda_bf16.h>
#include <math.h>
#include <stdint.h>

// ---------------- problem constants ----------------
#define DIMX   2048
#define NH     16
#define QLORA  1536
#define KVLORA 512
#define ROPE_D 64
#define QK_NOPE 128
#define QK_HEAD 192     // 128 + 64
#define V_HEAD 128
#define BSZ    2
#define SEQ    2048
#define NTOK   (BSZ*SEQ)        // 4096
#define KEFF   (KVLORA+ROPE_D)  // 576
#define EPSF   1e-6f

#define NEG_INF __int_as_float(0xff800000)

// ---------------- scratch (static device arrays; no cudaMalloc allowed) ----
__device__ float g_qa  [(size_t)NTOK * QLORA];
__device__ float g_q   [(size_t)NTOK * NH * QK_HEAD];
__device__ float g_kv  [(size_t)NTOK * KEFF];             // kvc 512 | k_pe 64
__device__ float g_qeff[(size_t)BSZ * NH * SEQ * KEFF];   // absorbed q 512 | roped q_pe 64
__device__ float g_scr [(size_t)BSZ * NH * SEQ * SEQ];    // scores / attn
__device__ float g_ao  [(size_t)BSZ * NH * SEQ * KVLORA];
__device__ float g_ov  [(size_t)NTOK * NH * V_HEAD];
__device__ float g_wnt [(size_t)NH * KVLORA * QK_NOPE];   // wkv_b_nope^T per head [c][d]
__device__ float g_kvt [(size_t)BSZ * KVLORA * SEQ];      // kvc^T per batch [c][t]

// ---------------- batch offset map: off = (z/div)*s1 + (z%mod)*s2 ----------
struct BMap { int div; long long s1; int mod; long long s2; };
__device__ __forceinline__ long long boff(const BMap m, int z) {
    return (long long)(z / m.div) * m.s1 + (long long)(z % m.mod) * m.s2;
}

// ---------------- helpers ----------------
__device__ __forceinline__ uint32_t smem_u32(const void* p) {
    uint32_t a;
    asm("{ .reg .u64 t; cvta.to.shared.u64 t, %1; cvt.u32.u64 %0, t; }" : "=r"(a) : "l"(p));
    return a;
}
// v = hi + lo with hi, lo bf16; pack pairs (even k in low half)
__device__ __forceinline__ void split2(float x, float y, uint32_t& hi, uint32_t& lo) {
    __nv_bfloat16 hx = __float2bfloat16_rn(x);
    __nv_bfloat16 hy = __float2bfloat16_rn(y);
    __nv_bfloat16 lx = __float2bfloat16_rn(x - __bfloat162float(hx));
    __nv_bfloat16 ly = __float2bfloat16_rn(y - __bfloat162float(hy));
    hi = (uint32_t)__bfloat16_as_ushort(hx) | ((uint32_t)__bfloat16_as_ushort(hy) << 16);
    lo = (uint32_t)__bfloat16_as_ushort(lx) | ((uint32_t)__bfloat16_as_ushort(ly) << 16);
}

// mma.sync m16n8k16 bf16, fp32 accumulate
#define MMABF(d, a, b) \
    asm volatile("mma.sync.aligned.m16n8k16.row.col.f32.bf16.bf16.f32 " \
        "{%0,%1,%2,%3}, {%4,%5,%6,%7}, {%8,%9}, {%0,%1,%2,%3};" \
        : "+f"((d)[0]), "+f"((d)[1]), "+f"((d)[2]), "+f"((d)[3]) \
        : "r"((a)[0]), "r"((a)[1]), "r"((a)[2]), "r"((a)[3]), \
          "r"((b)[0]), "r"((b)[1]))

#define LDM_X4(r0, r1, r2, r3, addr) \
    asm volatile("ldmatrix.sync.aligned.m8n8.x4.shared.b16 {%0,%1,%2,%3}, [%4];" \
        : "=r"(r0), "=r"(r1), "=r"(r2), "=r"(r3) : "r"(addr))

// ---------------- split-bf16 batched TN GEMM (near-fp32 precision) ---------
// C[m,n] = alpha * sum_k A[m,k] * B[n,k]  (+bias[n])
// A: [M,K] lda;  B: [N,K] ldb; fp32 K-major.
// Requirements: M % 128 == 0, K % 16 == 0, N % 2 == 0.
// trik: 0 = none, 1 = causal (skip tiles with n0 >= m0+128; softmax masks rest),
//       2 = k-limit (A[m,k]==0 for k>m => Kend = m0+128)
#define GBM 128
#define GBN 128
#define GBK 16
#define PBW 12          // smem words per 16-elem bf16 row (24 bf16 = 16 + 8 pad)
#define PLW (GBM*PBW)   // words per plane (1536)

__global__ void __launch_bounds__(256)
mma_gemm(float* __restrict__ Cb, const float* __restrict__ Ab,
         const float* __restrict__ Bb, const float* __restrict__ bias,
         float alpha, int trik, int M, int N, int K,
         int lda, int ldb, int ldc, BMap am, BMap bm, BMap cm)
{
    const int z = blockIdx.z;
    const int m0 = blockIdx.y * GBM;
    const int n0 = blockIdx.x * GBN;
    if (trik == 1 && n0 >= m0 + GBM) return;   // fully masked tile

    // [buf][plane][row*PBW + word]
    __shared__ uint32_t sA[2][2][PLW];
    __shared__ uint32_t sB[2][2][PLW];

    const float* A = Ab + boff(am, z);
    const float* B = Bb + boff(bm, z);
    float*       C = Cb + boff(cm, z);

    const int tid  = threadIdx.x;
    const int wid  = tid >> 5;
    const int lane = tid & 31;
    const int wm   = wid & 1;          // 2 warps in m
    const int wn   = wid >> 1;         // 4 warps in n
    const int g    = lane >> 2;        // group id (0..7)
    const int c    = lane & 3;         // thread in group (0..3)

    int Kend = K;
    if (trik == 2) { int lim = m0 + GBM; Kend = (lim < K) ? lim : K; }

    float acc[4][4][4];
    #pragma unroll
    for (int i = 0; i < 4; i++)
        #pragma unroll
        for (int j = 0; j < 4; j++)
            #pragma unroll
            for (int l = 0; l < 4; l++) acc[i][j][l] = 0.f;

    // ---- ldmatrix per-thread base addresses (bytes) ----
    // A: row = wm*64 + mt*16 + (lane&15), koff = (lane>>4)*4 words
    const uint32_t sA0 = smem_u32(&sA[0][0][0]);
    const uint32_t sB0 = smem_u32(&sB[0][0][0]);
    const uint32_t aAddr0 = sA0 + (((wm * 64 + (lane & 15)) * PBW + (lane >> 4) * 4) << 2);
    // B: row = wn*32 + pair*16 + (lane&7) + ((lane>>4)<<3), koff = ((lane>>3)&1)*4
    const uint32_t bAddr0 = sB0 + (((wn * 32 + (lane & 7) + ((lane >> 4) << 3)) * PBW
                                    + ((lane >> 3) & 1) * 4) << 2);

    // per-thread store slots: chunks tid and tid+256 of 512 (row = chunk>>2, q = chunk&3)
    float4 ra[2], rb[2];
    const int row_[2] = { tid >> 2, (tid + 256) >> 2 };
    const int q_[2]   = { tid & 3, (tid + 256) & 3 };

    auto prefetch = [&](int k0) {
        #pragma unroll
        for (int i = 0; i < 2; i++) {
            int row = row_[i], q = q_[i];
            ra[i] = *reinterpret_cast<const float4*>(&A[(size_t)(m0 + row) * lda + k0 + q * 4]);
            if (n0 + row < N)
                rb[i] = *reinterpret_cast<const float4*>(&B[(size_t)(n0 + row) * ldb + k0 + q * 4]);
            else
                rb[i] = make_float4(0.f, 0.f, 0.f, 0.f);
        }
    };
    auto stores = [&](int buf) {
        #pragma unroll
        for (int i = 0; i < 2; i++) {
            int w = row_[i] * PBW + q_[i] * 2;
            uint32_t h0, l0, h1, l1;
            split2(ra[i].x, ra[i].y, h0, l0);
            split2(ra[i].z, ra[i].w, h1, l1);
            sA[buf][0][w] = h0; sA[buf][0][w + 1] = h1;
            sA[buf][1][w] = l0; sA[buf][1][w + 1] = l1;
            split2(rb[i].x, rb[i].y, h0, l0);
            split2(rb[i].z, rb[i].w, h1, l1);
            sB[buf][0][w] = h0; sB[buf][0][w + 1] = h1;
            sB[buf][1][w] = l0; sB[buf][1][w + 1] = l1;
        }
    };

    prefetch(0);
    stores(0);
    __syncthreads();

    int buf = 0;
    for (int k0 = 0; k0 < Kend; k0 += GBK) {
        const bool last = (k0 + GBK >= Kend);
        if (!last) prefetch(k0 + GBK);

        // fragment loads via ldmatrix (buf offset in bytes: buf*2*PLW*4)
        const uint32_t bufA = aAddr0 + (uint32_t)(buf * 2 * PLW) * 4u;
        const uint32_t bufB = bAddr0 + (uint32_t)(buf * 2 * PLW) * 4u;
        uint32_t ah[4][4], al[4][4], bh[4][2], bl[4][2];
        #pragma unroll
        for (int mt = 0; mt < 4; mt++) {
            uint32_t a = bufA + (uint32_t)(mt * 16 * PBW) * 4u;
            LDM_X4(ah[mt][0], ah[mt][1], ah[mt][2], ah[mt][3], a);
            LDM_X4(al[mt][0], al[mt][1], al[mt][2], al[mt][3], a + PLW * 4u);
        }
        #pragma unroll
        for (int pr = 0; pr < 2; pr++) {
            uint32_t b = bufB + (uint32_t)(pr * 16 * PBW) * 4u;
            LDM_X4(bh[2 * pr][0], bh[2 * pr][1], bh[2 * pr + 1][0], bh[2 * pr + 1][1], b);
            LDM_X4(bl[2 * pr][0], bl[2 * pr][1], bl[2 * pr + 1][0], bl[2 * pr + 1][1], b + PLW * 4u);
        }

        // pass 1: hi*hi; pass 2: hi*lo; pass 3: lo*hi (16-MMA dependency distance)
        #pragma unroll
        for (int mt = 0; mt < 4; mt++)
            #pragma unroll
            for (int nt = 0; nt < 4; nt++)
                MMABF(acc[mt][nt], ah[mt], bh[nt]);
        #pragma unroll
        for (int mt = 0; mt < 4; mt++)
            #pragma unroll
            for (int nt = 0; nt < 4; nt++)
                MMABF(acc[mt][nt], ah[mt], bl[nt]);
        #pragma unroll
        for (int mt = 0; mt < 4; mt++)
            #pragma unroll
            for (int nt = 0; nt < 4; nt++)
                MMABF(acc[mt][nt], al[mt], bh[nt]);

        if (!last) stores(buf ^ 1);
        __syncthreads();
        buf ^= 1;
    }

    // epilogue
    #pragma unroll
    for (int mt = 0; mt < 4; mt++) {
        int m = m0 + wm * 64 + mt * 16 + g;
        #pragma unroll
        for (int nt = 0; nt < 4; nt++) {
            int n = n0 + wn * 32 + nt * 8 + 2 * c;
            if (n >= N) continue;
            float b0 = 0.f, b1 = 0.f;
            if (bias) { b0 = bias[n]; b1 = bias[n + 1]; }
            float2 v0, v1;
            v0.x = acc[mt][nt][0] * alpha + b0;
            v0.y = acc[mt][nt][1] * alpha + b1;
            v1.x = acc[mt][nt][2] * alpha + b0;
            v1.y = acc[mt][nt][3] * alpha + b1;
            *reinterpret_cast<float2*>(&C[(size_t)m * ldc + n]) = v0;
            *reinterpret_cast<float2*>(&C[(size_t)(m + 8) * ldc + n]) = v1;
        }
    }
}

// ---------------- transposes ----------------
// wnt[h][c][d] = wkv_b[h][d][c]   (d < 128, c < 512; wkv_b row block = 256 rows)
__global__ void wnt_kernel(const float* __restrict__ w, float* __restrict__ wt) {
    __shared__ float t[32][33];
    int h = blockIdx.z;
    int c0 = blockIdx.x * 32, d0 = blockIdx.y * 32;
    int tx = threadIdx.x, ty = threadIdx.y;
    const float* src = w + (size_t)h * 256 * KVLORA;
    #pragma unroll
    for (int i = 0; i < 32; i += 8)
        t[ty + i][tx] = src[(size_t)(d0 + ty + i) * KVLORA + c0 + tx];
    __syncthreads();
    float* dst = wt + (size_t)h * KVLORA * QK_NOPE;
    #pragma unroll
    for (int i = 0; i < 32; i += 8)
        dst[(size_t)(c0 + ty + i) * QK_NOPE + d0 + tx] = t[tx][ty + i];
}

// kvt[b][c][t] = kv[b*SEQ + t][c]   (c < 512)
__global__ void kvt_kernel(const float* __restrict__ kv, float* __restrict__ kvt) {
    __shared__ float t[32][33];
    int b = blockIdx.z;
    int t0 = blockIdx.x * 32, c0 = blockIdx.y * 32;
    int tx = threadIdx.x, ty = threadIdx.y;
    const float* src = kv + (size_t)b * SEQ * KEFF;
    #pragma unroll
    for (int i = 0; i < 32; i += 8)
        t[ty + i][tx] = src[(size_t)(t0 + ty + i) * KEFF + c0 + tx];
    __syncthreads();
    float* dst = kvt + (size_t)b * KVLORA * SEQ;
    #pragma unroll
    for (int i = 0; i < 32; i += 8)
        dst[(size_t)(c0 + ty + i) * SEQ + t0 + tx] = t[tx][ty + i];
}

// ---------------- block reductions ----------------
__device__ __forceinline__ float block_reduce_sum(float v) {
    __shared__ float sh[32];
    int lane = threadIdx.x & 31, w = threadIdx.x >> 5;
    __syncthreads();
    #pragma unroll
    for (int o = 16; o; o >>= 1) v += __shfl_down_sync(0xffffffffu, v, o);
    if (lane == 0) sh[w] = v;
    __syncthreads();
    int nw = blockDim.x >> 5;
    v = (threadIdx.x < (unsigned)nw) ? sh[threadIdx.x] : 0.f;
    if (w == 0) {
        #pragma unroll
        for (int o = 16; o; o >>= 1) v += __shfl_down_sync(0xffffffffu, v, o);
        if (lane == 0) sh[0] = v;
    }
    __syncthreads();
    return sh[0];
}
__device__ __forceinline__ float block_reduce_max(float v) {
    __shared__ float sh[32];
    int lane = threadIdx.x & 31, w = threadIdx.x >> 5;
    __syncthreads();
    #pragma unroll
    for (int o = 16; o; o >>= 1) v = fmaxf(v, __shfl_down_sync(0xffffffffu, v, o));
    if (lane == 0) sh[w] = v;
    __syncthreads();
    int nw = blockDim.x >> 5;
    v = (threadIdx.x < (unsigned)nw) ? sh[threadIdx.x] : NEG_INF;
    if (w == 0) {
        #pragma unroll
        for (int o = 16; o; o >>= 1) v = fmaxf(v, __shfl_down_sync(0xffffffffu, v, o));
        if (lane == 0) sh[0] = v;
    }
    __syncthreads();
    return sh[0];
}

// ---------------- rmsnorm over a row of length n (in place) ----------------
__global__ void rmsnorm_kernel(float* __restrict__ x, const float* __restrict__ w, int n) {
    float* p = x + (long long)blockIdx.x * n;
    float ss = 0.f;
    for (int i = threadIdx.x; i < n; i += blockDim.x) { float v = p[i]; ss += v * v; }
    float tot = block_reduce_sum(ss);
    float scale = rsqrtf(tot / (float)n + EPSF);
    for (int i = threadIdx.x; i < n; i += blockDim.x) p[i] = p[i] * scale * w[i];
}

// ---------------- kv post: rmsnorm first 512, rope last 64 (in place) ------
__global__ void kv_post_kernel(float* __restrict__ kv, const float* __restrict__ w,
                               const float* __restrict__ freqs) {
    int t = blockIdx.x;
    int s = t % SEQ;
    float* p = kv + (long long)t * KEFF;
    float ss = 0.f;
    for (int i = threadIdx.x; i < KVLORA; i += blockDim.x) { float v = p[i]; ss += v * v; }
    float tot = block_reduce_sum(ss);
    float scale = rsqrtf(tot / (float)KVLORA + EPSF);
    for (int i = threadIdx.x; i < KVLORA; i += blockDim.x) p[i] = p[i] * scale * w[i];
    if (threadIdx.x < ROPE_D / 2) {
        int i = threadIdx.x;
        float c  = freqs[s * ROPE_D + 2 * i];
        float sn = freqs[s * ROPE_D + 2 * i + 1];
        float x0 = p[KVLORA + 2 * i], x1 = p[KVLORA + 2 * i + 1];
        p[KVLORA + 2 * i]     = x0 * c - x1 * sn;
        p[KVLORA + 2 * i + 1] = x1 * c + x0 * sn;
    }
}

// ---------------- rope q_pe -> qeff[..., 512:576] ----------------
__global__ void qrope_kernel(const float* __restrict__ q, float* __restrict__ qeff,
                             const float* __restrict__ freqs) {
    int t = blockIdx.x;
    int b = t / SEQ, s = t % SEQ;
    int h = threadIdx.x >> 5;
    int i = threadIdx.x & 31;
    float c  = freqs[s * ROPE_D + 2 * i];
    float sn = freqs[s * ROPE_D + 2 * i + 1];
    const float* qp = q + (long long)t * NH * QK_HEAD + h * QK_HEAD + QK_NOPE;
    float x0 = qp[2 * i], x1 = qp[2 * i + 1];
    float* o = qeff + ((long long)(b * NH + h) * SEQ + s) * KEFF + KVLORA;
    o[2 * i]     = x0 * c - x1 * sn;
    o[2 * i + 1] = x1 * c + x0 * sn;
}

// ---------------- causal row softmax (valid length s+1; zero above) --------
__global__ void softmax_kernel(float* __restrict__ S) {
    const int n = SEQ;
    int s = blockIdx.x % SEQ;       // row position within its (b,h) matrix
    float* p = S + (long long)blockIdx.x * n;
    float e[8];
    float mx = NEG_INF;
    #pragma unroll
    for (int k = 0; k < 8; k++) {
        int idx = threadIdx.x + k * 256;
        e[k] = (idx <= s) ? p[idx] : NEG_INF;
        mx = fmaxf(mx, e[k]);
    }
    mx = block_reduce_max(mx);
    float sum = 0.f;
    #pragma unroll
    for (int k = 0; k < 8; k++) {
        e[k] = expf(e[k] - mx);     // exp(-inf) = 0 for masked entries
        sum += e[k];
    }
    sum = block_reduce_sum(sum);
    float inv = 1.f / sum;
    #pragma unroll
    for (int k = 0; k < 8; k++) {
        int idx = threadIdx.x + k * 256;
        p[idx] = (idx <= s) ? e[k] * inv : 0.f;
    }
}

// ---------------- launch ----------------
extern "C" void kernel_launch(void* const* d_in, const int* in_sizes, int n_in,
                              void* d_out, int out_size) {
    int pbase = (n_in > 3 && in_sizes[3] == 1) ? 4 : 3;
    const float* x         = (const float*)d_in[0];
    const float* freqs     = (const float*)d_in[1];
    const float* wq_a_w    = (const float*)d_in[pbase + 0];
    const float* wq_a_b    = (const float*)d_in[pbase + 1];
    const float* q_norm_w  = (const float*)d_in[pbase + 2];
    const float* wq_b_w    = (const float*)d_in[pbase + 3];
    const float* wq_b_b    = (const float*)d_in[pbase + 4];
    const float* wkv_a_w   = (const float*)d_in[pbase + 5];
    const float* wkv_a_b   = (const float*)d_in[pbase + 6];
    const float* kv_norm_w = (const float*)d_in[pbase + 7];
    const float* wkv_b_w   = (const float*)d_in[pbase + 8];
    const float* wo_w      = (const float*)d_in[pbase + 9];
    const float* wo_b      = (const float*)d_in[pbase + 10];
    float* out = (float*)d_out;

    float *qa, *q, *kv, *qeff, *scr, *ao, *ov, *wnt, *kvt;
    cudaGetSymbolAddress((void**)&qa,   g_qa);
    cudaGetSymbolAddress((void**)&q,    g_q);
    cudaGetSymbolAddress((void**)&kv,   g_kv);
    cudaGetSymbolAddress((void**)&qeff, g_qeff);
    cudaGetSymbolAddress((void**)&scr,  g_scr);
    cudaGetSymbolAddress((void**)&ao,   g_ao);
    cudaGetSymbolAddress((void**)&ov,   g_ov);
    cudaGetSymbolAddress((void**)&wnt,  g_wnt);
    cudaGetSymbolAddress((void**)&kvt,  g_kvt);

    const BMap id = {1, 0, 1, 0};
    const dim3 blk(256);

    // 0) transpose wkv_b nope blocks: wnt[h][c][d]
    wnt_kernel<<<dim3(KVLORA / 32, QK_NOPE / 32, NH), dim3(32, 8)>>>(wkv_b_w, wnt);

    // 1) qa = x @ wq_a_w^T + b
    mma_gemm<<<dim3(12, 32, 1), blk>>>(qa, x, wq_a_w, wq_a_b, 1.f, 0,
        NTOK, QLORA, DIMX, DIMX, DIMX, QLORA, id, id, id);

    // 2) rmsnorm(qa)
    rmsnorm_kernel<<<NTOK, 256>>>(qa, q_norm_w, QLORA);

    // 3) q = qa @ wq_b_w^T + b
    mma_gemm<<<dim3(24, 32, 1), blk>>>(q, qa, wq_b_w, wq_b_b, 1.f, 0,
        NTOK, NH * QK_HEAD, QLORA, QLORA, QLORA, NH * QK_HEAD, id, id, id);

    // 4) kv = x @ wkv_a_w^T + b
    mma_gemm<<<dim3(5, 32, 1), blk>>>(kv, x, wkv_a_w, wkv_a_b, 1.f, 0,
        NTOK, KEFF, DIMX, DIMX, DIMX, KEFF, id, id, id);

    // 5) kvc = rmsnorm(kv[:,:512]); k_pe = rope(kv[:,512:])
    kv_post_kernel<<<NTOK, 256>>>(kv, kv_norm_w, freqs);

    // 5b) kvt[b][c][t] = kvc^T
    kvt_kernel<<<dim3(SEQ / 32, KVLORA / 32, BSZ), dim3(32, 8)>>>(kv, kvt);

    // 6) qeff[...,512:576] = rope(q_pe)
    qrope_kernel<<<NTOK, 512>>>(q, qeff, freqs);

    // 7) qeff[z,:, :512] = q_nope @ wnt[h]^T    (TN: B = wnt[h] [512,128])
    {
        BMap am = {NH, (long long)SEQ * NH * QK_HEAD, NH, QK_HEAD};
        BMap bm = {1, 0, NH, (long long)KVLORA * QK_NOPE};
        BMap cm = {1, (long long)SEQ * KEFF, 1, 0};
        mma_gemm<<<dim3(4, 16, 32), blk>>>(qeff, q, wnt, nullptr, 1.f, 0,
            SEQ, KVLORA, QK_NOPE, NH * QK_HEAD, QK_NOPE, KEFF, am, bm, cm);
    }

    // 8) scores = scale * Qeff @ Keff^T, causal (TN: B = kv rows [t,576])
    {
        BMap am = {1, (long long)SEQ * KEFF, 1, 0};
        BMap bm = {NH, (long long)SEQ * KEFF, 1, 0};
        BMap cm = {1, (long long)SEQ * SEQ, 1, 0};
        const float scale = 0.07216878364870323f;    // 192^-0.5
        mma_gemm<<<dim3(16, 16, 32), blk>>>(scr, qeff, kv, nullptr, scale, 1,
            SEQ, SEQ, KEFF, KEFF, KEFF, SEQ, am, bm, cm);
    }

    // 9) causal softmax rows
    softmax_kernel<<<BSZ * NH * SEQ, 256>>>(scr);

    // 10) ao = attn @ kvc   (TN: B = kvt[b] [512, 2048], k-limited)
    {
        BMap am = {1, (long long)SEQ * SEQ, 1, 0};
        BMap bm = {NH, (long long)KVLORA * SEQ, 1, 0};
        BMap cm = {1, (long long)SEQ * KVLORA, 1, 0};
        mma_gemm<<<dim3(4, 16, 32), blk>>>(ao, scr, kvt, nullptr, 1.f, 2,
            SEQ, KVLORA, SEQ, SEQ, SEQ, KVLORA, am, bm, cm);
    }

    // 11) ov = ao @ wv^T  (TN: B = wkv_b[h][128:256,:] rows [d,512])
    {
        BMap am = {1, (long long)SEQ * KVLORA, 1, 0};
        BMap bm = {1, 0, NH, (long long)256 * KVLORA};
        BMap cm = {NH, (long long)SEQ * NH * V_HEAD, NH, V_HEAD};
        mma_gemm<<<dim3(1, 16, 32), blk>>>(ov, ao, wkv_b_w + (long long)QK_NOPE * KVLORA,
            nullptr, 1.f, 0,
            SEQ, V_HEAD, KVLORA, KVLORA, KVLORA, NH * V_HEAD, am, bm, cm);
    }

    // 12) out = ov @ wo_w^T + wo_b
    mma_gemm<<<dim3(16, 32, 1), blk>>>(out, ov, wo_w, wo_b, 1.f, 0,
        NTOK, DIMX, NH * V_HEAD, NH * V_HEAD, NH * V_HEAD, DIMX, id, id, id);
}

// round 12
// speedup vs baseline: 1.2490x; 1.0016x over previous
#include <cuda_runtime.h>
#include <cuda_bf16.h>
#include <math.h>
#include <stdint.h>

// ---------------- problem constants ----------------
#define DIMX   2048
#define NH     16
#define QLORA  1536
#define KVLORA 512
#define ROPE_D 64
#define QK_NOPE 128
#define QK_HEAD 192     // 128 + 64
#define V_HEAD 128
#define BSZ    2
#define SEQ    2048
#define NTOK   (BSZ*SEQ)        // 4096
#define KEFF   (KVLORA+ROPE_D)  // 576
#define EPSF   1e-6f

#define NEG_INF __int_as_float(0xff800000)

// ---------------- scratch (static device arrays; no cudaMalloc allowed) ----
__device__ float g_qa  [(size_t)NTOK * QLORA];
__device__ float g_q   [(size_t)NTOK * NH * QK_HEAD];
__device__ float g_kv  [(size_t)NTOK * KEFF];             // kvc 512 | k_pe 64
__device__ float g_qeff[(size_t)BSZ * NH * SEQ * KEFF];   // absorbed q 512 | roped q_pe 64
__device__ float g_scr [(size_t)BSZ * NH * SEQ * SEQ];    // scores / attn
__device__ float g_ao  [(size_t)BSZ * NH * SEQ * KVLORA];
__device__ float g_ov  [(size_t)NTOK * NH * V_HEAD];
__device__ float g_wnt [(size_t)NH * KVLORA * QK_NOPE];   // wkv_b_nope^T per head [c][d]
__device__ float g_kvt [(size_t)BSZ * KVLORA * SEQ];      // kvc^T per batch [c][t]

// ---------------- batch offset map: off = (z/div)*s1 + (z%mod)*s2 ----------
struct BMap { int div; long long s1; int mod; long long s2; };
__device__ __forceinline__ long long boff(const BMap m, int z) {
    return (long long)(z / m.div) * m.s1 + (long long)(z % m.mod) * m.s2;
}

// ---------------- helpers ----------------
__device__ __forceinline__ uint32_t smem_u32(const void* p) {
    uint32_t a;
    asm("{ .reg .u64 t; cvta.to.shared.u64 t, %1; cvt.u32.u64 %0, t; }" : "=r"(a) : "l"(p));
    return a;
}
// v = hi + lo with hi, lo bf16; pack pairs (even k in low half)
__device__ __forceinline__ void split2(float x, float y, uint32_t& hi, uint32_t& lo) {
    __nv_bfloat16 hx = __float2bfloat16_rn(x);
    __nv_bfloat16 hy = __float2bfloat16_rn(y);
    __nv_bfloat16 lx = __float2bfloat16_rn(x - __bfloat162float(hx));
    __nv_bfloat16 ly = __float2bfloat16_rn(y - __bfloat162float(hy));
    hi = (uint32_t)__bfloat16_as_ushort(hx) | ((uint32_t)__bfloat16_as_ushort(hy) << 16);
    lo = (uint32_t)__bfloat16_as_ushort(lx) | ((uint32_t)__bfloat16_as_ushort(ly) << 16);
}

// mma.sync m16n8k16 bf16, fp32 accumulate
#define MMABF(d, a, b) \
    asm volatile("mma.sync.aligned.m16n8k16.row.col.f32.bf16.bf16.f32 " \
        "{%0,%1,%2,%3}, {%4,%5,%6,%7}, {%8,%9}, {%0,%1,%2,%3};" \
        : "+f"((d)[0]), "+f"((d)[1]), "+f"((d)[2]), "+f"((d)[3]) \
        : "r"((a)[0]), "r"((a)[1]), "r"((a)[2]), "r"((a)[3]), \
          "r"((b)[0]), "r"((b)[1]))

#define LDM_X4(r0, r1, r2, r3, addr) \
    asm volatile("ldmatrix.sync.aligned.m8n8.x4.shared.b16 {%0,%1,%2,%3}, [%4];" \
        : "=r"(r0), "=r"(r1), "=r"(r2), "=r"(r3) : "r"(addr))

// ---------------- split-bf16 batched TN GEMM (near-fp32 precision) ---------
// C[m,n] = alpha * sum_k A[m,k] * B[n,k]  (+bias[n])
// A: [M,K] lda;  B: [N,K] ldb; fp32 K-major.
// Requirements: M % 128 == 0, K % 16 == 0, N % 2 == 0.
// trik: 0 = none, 1 = causal (skip tiles with n0 >= m0+128; softmax masks rest),
//       2 = k-limit (A[m,k]==0 for k>m => Kend = m0+128)
#define GBM 128
#define GBN 128
#define GBK 16
#define PBW 12          // smem words per 16-elem bf16 row (24 bf16 = 16 + 8 pad)
#define PLW (GBM*PBW)   // words per plane (1536)

__global__ void __launch_bounds__(256)
mma_gemm(float* __restrict__ Cb, const float* __restrict__ Ab,
         const float* __restrict__ Bb, const float* __restrict__ bias,
         float alpha, int trik, int M, int N, int K,
         int lda, int ldb, int ldc, BMap am, BMap bm, BMap cm)
{
    const int z = blockIdx.z;
    const int m0 = blockIdx.y * GBM;
    const int n0 = blockIdx.x * GBN;
    if (trik == 1 && n0 >= m0 + GBM) return;   // fully masked tile

    // [buf][plane][row*PBW + word]
    __shared__ uint32_t sA[2][2][PLW];
    __shared__ uint32_t sB[2][2][PLW];

    const float* A = Ab + boff(am, z);
    const float* B = Bb + boff(bm, z);
    float*       C = Cb + boff(cm, z);

    const int tid  = threadIdx.x;
    const int wid  = tid >> 5;
    const int lane = tid & 31;
    const int wm   = wid & 1;          // 2 warps in m
    const int wn   = wid >> 1;         // 4 warps in n
    const int g    = lane >> 2;        // group id (0..7)
    const int c    = lane & 3;         // thread in group (0..3)

    int Kend = K;
    if (trik == 2) { int lim = m0 + GBM; Kend = (lim < K) ? lim : K; }

    float acc[4][4][4];
    #pragma unroll
    for (int i = 0; i < 4; i++)
        #pragma unroll
        for (int j = 0; j < 4; j++)
            #pragma unroll
            for (int l = 0; l < 4; l++) acc[i][j][l] = 0.f;

    // ---- ldmatrix per-thread base addresses (bytes) ----
    // A: row = wm*64 + mt*16 + (lane&15), koff = (lane>>4)*4 words
    const uint32_t sA0 = smem_u32(&sA[0][0][0]);
    const uint32_t sB0 = smem_u32(&sB[0][0][0]);
    const uint32_t aAddr0 = sA0 + (((wm * 64 + (lane & 15)) * PBW + (lane >> 4) * 4) << 2);
    // B: row = wn*32 + pair*16 + (lane&7) + ((lane>>4)<<3), koff = ((lane>>3)&1)*4
    const uint32_t bAddr0 = sB0 + (((wn * 32 + (lane & 7) + ((lane >> 4) << 3)) * PBW
                                    + ((lane >> 3) & 1) * 4) << 2);

    // per-thread store slots: chunks tid and tid+256 of 512 (row = chunk>>2, q = chunk&3)
    float4 ra[2], rb[2];
    const int row_[2] = { tid >> 2, (tid + 256) >> 2 };
    const int q_[2]   = { tid & 3, (tid + 256) & 3 };

    auto prefetch = [&](int k0) {
        #pragma unroll
        for (int i = 0; i < 2; i++) {
            int row = row_[i], q = q_[i];
            ra[i] = *reinterpret_cast<const float4*>(&A[(size_t)(m0 + row) * lda + k0 + q * 4]);
            if (n0 + row < N)
                rb[i] = *reinterpret_cast<const float4*>(&B[(size_t)(n0 + row) * ldb + k0 + q * 4]);
            else
                rb[i] = make_float4(0.f, 0.f, 0.f, 0.f);
        }
    };
    auto stores = [&](int buf) {
        #pragma unroll
        for (int i = 0; i < 2; i++) {
            int w = row_[i] * PBW + q_[i] * 2;
            uint32_t h0, l0, h1, l1;
            split2(ra[i].x, ra[i].y, h0, l0);
            split2(ra[i].z, ra[i].w, h1, l1);
            sA[buf][0][w] = h0; sA[buf][0][w + 1] = h1;
            sA[buf][1][w] = l0; sA[buf][1][w + 1] = l1;
            split2(rb[i].x, rb[i].y, h0, l0);
            split2(rb[i].z, rb[i].w, h1, l1);
            sB[buf][0][w] = h0; sB[buf][0][w + 1] = h1;
            sB[buf][1][w] = l0; sB[buf][1][w + 1] = l1;
        }
    };

    prefetch(0);
    stores(0);
    __syncthreads();

    int buf = 0;
    for (int k0 = 0; k0 < Kend; k0 += GBK) {
        const bool last = (k0 + GBK >= Kend);
        if (!last) prefetch(k0 + GBK);

        // fragment loads via ldmatrix (buf offset in bytes: buf*2*PLW*4)
        const uint32_t bufA = aAddr0 + (uint32_t)(buf * 2 * PLW) * 4u;
        const uint32_t bufB = bAddr0 + (uint32_t)(buf * 2 * PLW) * 4u;
        uint32_t ah[4][4], al[4][4], bh[4][2], bl[4][2];
        #pragma unroll
        for (int mt = 0; mt < 4; mt++) {
            uint32_t a = bufA + (uint32_t)(mt * 16 * PBW) * 4u;
            LDM_X4(ah[mt][0], ah[mt][1], ah[mt][2], ah[mt][3], a);
            LDM_X4(al[mt][0], al[mt][1], al[mt][2], al[mt][3], a + PLW * 4u);
        }
        #pragma unroll
        for (int pr = 0; pr < 2; pr++) {
            uint32_t b = bufB + (uint32_t)(pr * 16 * PBW) * 4u;
            LDM_X4(bh[2 * pr][0], bh[2 * pr][1], bh[2 * pr + 1][0], bh[2 * pr + 1][1], b);
            LDM_X4(bl[2 * pr][0], bl[2 * pr][1], bl[2 * pr + 1][0], bl[2 * pr + 1][1], b + PLW * 4u);
        }

        // pass 1: hi*hi; pass 2: hi*lo; pass 3: lo*hi (16-MMA dependency distance)
        #pragma unroll
        for (int mt = 0; mt < 4; mt++)
            #pragma unroll
            for (int nt = 0; nt < 4; nt++)
                MMABF(acc[mt][nt], ah[mt], bh[nt]);
        #pragma unroll
        for (int mt = 0; mt < 4; mt++)
            #pragma unroll
            for (int nt = 0; nt < 4; nt++)
                MMABF(acc[mt][nt], ah[mt], bl[nt]);
        #pragma unroll
        for (int mt = 0; mt < 4; mt++)
            #pragma unroll
            for (int nt = 0; nt < 4; nt++)
                MMABF(acc[mt][nt], al[mt], bh[nt]);

        if (!last) stores(buf ^ 1);
        __syncthreads();
        buf ^= 1;
    }

    // epilogue
    #pragma unroll
    for (int mt = 0; mt < 4; mt++) {
        int m = m0 + wm * 64 + mt * 16 + g;
        #pragma unroll
        for (int nt = 0; nt < 4; nt++) {
            int n = n0 + wn * 32 + nt * 8 + 2 * c;
            if (n >= N) continue;
            float b0 = 0.f, b1 = 0.f;
            if (bias) { b0 = bias[n]; b1 = bias[n + 1]; }
            float2 v0, v1;
            v0.x = acc[mt][nt][0] * alpha + b0;
            v0.y = acc[mt][nt][1] * alpha + b1;
            v1.x = acc[mt][nt][2] * alpha + b0;
            v1.y = acc[mt][nt][3] * alpha + b1;
            *reinterpret_cast<float2*>(&C[(size_t)m * ldc + n]) = v0;
            *reinterpret_cast<float2*>(&C[(size_t)(m + 8) * ldc + n]) = v1;
        }
    }
}

// ---------------- transposes ----------------
// wnt[h][c][d] = wkv_b[h][d][c]   (d < 128, c < 512; wkv_b row block = 256 rows)
__global__ void wnt_kernel(const float* __restrict__ w, float* __restrict__ wt) {
    __shared__ float t[32][33];
    int h = blockIdx.z;
    int c0 = blockIdx.x * 32, d0 = blockIdx.y * 32;
    int tx = threadIdx.x, ty = threadIdx.y;
    const float* src = w + (size_t)h * 256 * KVLORA;
    #pragma unroll
    for (int i = 0; i < 32; i += 8)
        t[ty + i][tx] = src[(size_t)(d0 + ty + i) * KVLORA + c0 + tx];
    __syncthreads();
    float* dst = wt + (size_t)h * KVLORA * QK_NOPE;
    #pragma unroll
    for (int i = 0; i < 32; i += 8)
        dst[(size_t)(c0 + ty + i) * QK_NOPE + d0 + tx] = t[tx][ty + i];
}

// kvt[b][c][t] = kv[b*SEQ + t][c]   (c < 512)
__global__ void kvt_kernel(const float* __restrict__ kv, float* __restrict__ kvt) {
    __shared__ float t[32][33];
    int b = blockIdx.z;
    int t0 = blockIdx.x * 32, c0 = blockIdx.y * 32;
    int tx = threadIdx.x, ty = threadIdx.y;
    const float* src = kv + (size_t)b * SEQ * KEFF;
    #pragma unroll
    for (int i = 0; i < 32; i += 8)
        t[ty + i][tx] = src[(size_t)(t0 + ty + i) * KEFF + c0 + tx];
    __syncthreads();
    float* dst = kvt + (size_t)b * KVLORA * SEQ;
    #pragma unroll
    for (int i = 0; i < 32; i += 8)
        dst[(size_t)(c0 + ty + i) * SEQ + t0 + tx] = t[tx][ty + i];
}

// ---------------- block reductions ----------------
__device__ __forceinline__ float block_reduce_sum(float v) {
    __shared__ float sh[32];
    int lane = threadIdx.x & 31, w = threadIdx.x >> 5;
    __syncthreads();
    #pragma unroll
    for (int o = 16; o; o >>= 1) v += __shfl_down_sync(0xffffffffu, v, o);
    if (lane == 0) sh[w] = v;
    __syncthreads();
    int nw = blockDim.x >> 5;
    v = (threadIdx.x < (unsigned)nw) ? sh[threadIdx.x] : 0.f;
    if (w == 0) {
        #pragma unroll
        for (int o = 16; o; o >>= 1) v += __shfl_down_sync(0xffffffffu, v, o);
        if (lane == 0) sh[0] = v;
    }
    __syncthreads();
    return sh[0];
}
__device__ __forceinline__ float block_reduce_max(float v) {
    __shared__ float sh[32];
    int lane = threadIdx.x & 31, w = threadIdx.x >> 5;
    __syncthreads();
    #pragma unroll
    for (int o = 16; o; o >>= 1) v = fmaxf(v, __shfl_down_sync(0xffffffffu, v, o));
    if (lane == 0) sh[w] = v;
    __syncthreads();
    int nw = blockDim.x >> 5;
    v = (threadIdx.x < (unsigned)nw) ? sh[threadIdx.x] : NEG_INF;
    if (w == 0) {
        #pragma unroll
        for (int o = 16; o; o >>= 1) v = fmaxf(v, __shfl_down_sync(0xffffffffu, v, o));
        if (lane == 0) sh[0] = v;
    }
    __syncthreads();
    return sh[0];
}

// ---------------- rmsnorm over a row of length n (in place) ----------------
__global__ void rmsnorm_kernel(float* __restrict__ x, const float* __restrict__ w, int n) {
    float* p = x + (long long)blockIdx.x * n;
    float ss = 0.f;
    for (int i = threadIdx.x; i < n; i += blockDim.x) { float v = p[i]; ss += v * v; }
    float tot = block_reduce_sum(ss);
    float scale = rsqrtf(tot / (float)n + EPSF);
    for (int i = threadIdx.x; i < n; i += blockDim.x) p[i] = p[i] * scale * w[i];
}

// ---------------- kv post: rmsnorm first 512, rope last 64 (in place) ------
__global__ void kv_post_kernel(float* __restrict__ kv, const float* __restrict__ w,
                               const float* __restrict__ freqs) {
    int t = blockIdx.x;
    int s = t % SEQ;
    float* p = kv + (long long)t * KEFF;
    float ss = 0.f;
    for (int i = threadIdx.x; i < KVLORA; i += blockDim.x) { float v = p[i]; ss += v * v; }
    float tot = block_reduce_sum(ss);
    float scale = rsqrtf(tot / (float)KVLORA + EPSF);
    for (int i = threadIdx.x; i < KVLORA; i += blockDim.x) p[i] = p[i] * scale * w[i];
    if (threadIdx.x < ROPE_D / 2) {
        int i = threadIdx.x;
        float c  = freqs[s * ROPE_D + 2 * i];
        float sn = freqs[s * ROPE_D + 2 * i + 1];
        float x0 = p[KVLORA + 2 * i], x1 = p[KVLORA + 2 * i + 1];
        p[KVLORA + 2 * i]     = x0 * c - x1 * sn;
        p[KVLORA + 2 * i + 1] = x1 * c + x0 * sn;
    }
}

// ---------------- rope q_pe -> qeff[..., 512:576] ----------------
__global__ void qrope_kernel(const float* __restrict__ q, float* __restrict__ qeff,
                             const float* __restrict__ freqs) {
    int t = blockIdx.x;
    int b = t / SEQ, s = t % SEQ;
    int h = threadIdx.x >> 5;
    int i = threadIdx.x & 31;
    float c  = freqs[s * ROPE_D + 2 * i];
    float sn = freqs[s * ROPE_D + 2 * i + 1];
    const float* qp = q + (long long)t * NH * QK_HEAD + h * QK_HEAD + QK_NOPE;
    float x0 = qp[2 * i], x1 = qp[2 * i + 1];
    float* o = qeff + ((long long)(b * NH + h) * SEQ + s) * KEFF + KVLORA;
    o[2 * i]     = x0 * c - x1 * sn;
    o[2 * i + 1] = x1 * c + x0 * sn;
}

// ---------------- causal row softmax (valid length s+1; zero above) --------
__global__ void softmax_kernel(float* __restrict__ S) {
    const int n = SEQ;
    int s = blockIdx.x % SEQ;       // row position within its (b,h) matrix
    float* p = S + (long long)blockIdx.x * n;
    float e[8];
    float mx = NEG_INF;
    #pragma unroll
    for (int k = 0; k < 8; k++) {
        int idx = threadIdx.x + k * 256;
        e[k] = (idx <= s) ? p[idx] : NEG_INF;
        mx = fmaxf(mx, e[k]);
    }
    mx = block_reduce_max(mx);
    float sum = 0.f;
    #pragma unroll
    for (int k = 0; k < 8; k++) {
        e[k] = expf(e[k] - mx);     // exp(-inf) = 0 for masked entries
        sum += e[k];
    }
    sum = block_reduce_sum(sum);
    float inv = 1.f / sum;
    #pragma unroll
    for (int k = 0; k < 8; k++) {
        int idx = threadIdx.x + k * 256;
        p[idx] = (idx <= s) ? e[k] * inv : 0.f;
    }
}

// ---------------- launch ----------------
extern "C" void kernel_launch(void* const* d_in, const int* in_sizes, int n_in,
                              void* d_out, int out_size) {
    int pbase = (n_in > 3 && in_sizes[3] == 1) ? 4 : 3;
    const float* x         = (const float*)d_in[0];
    const float* freqs     = (const float*)d_in[1];
    const float* wq_a_w    = (const float*)d_in[pbase + 0];
    const float* wq_a_b    = (const float*)d_in[pbase + 1];
    const float* q_norm_w  = (const float*)d_in[pbase + 2];
    const float* wq_b_w    = (const float*)d_in[pbase + 3];
    const float* wq_b_b    = (const float*)d_in[pbase + 4];
    const float* wkv_a_w   = (const float*)d_in[pbase + 5];
    const float* wkv_a_b   = (const float*)d_in[pbase + 6];
    const float* kv_norm_w = (const float*)d_in[pbase + 7];
    const float* wkv_b_w   = (const float*)d_in[pbase + 8];
    const float* wo_w      = (const float*)d_in[pbase + 9];
    const float* wo_b      = (const float*)d_in[pbase + 10];
    float* out = (float*)d_out;

    float *qa, *q, *kv, *qeff, *scr, *ao, *ov, *wnt, *kvt;
    cudaGetSymbolAddress((void**)&qa,   g_qa);
    cudaGetSymbolAddress((void**)&q,    g_q);
    cudaGetSymbolAddress((void**)&kv,   g_kv);
    cudaGetSymbolAddress((void**)&qeff, g_qeff);
    cudaGetSymbolAddress((void**)&scr,  g_scr);
    cudaGetSymbolAddress((void**)&ao,   g_ao);
    cudaGetSymbolAddress((void**)&ov,   g_ov);
    cudaGetSymbolAddress((void**)&wnt,  g_wnt);
    cudaGetSymbolAddress((void**)&kvt,  g_kvt);

    const BMap id = {1, 0, 1, 0};
    const dim3 blk(256);

    // 0) transpose wkv_b nope blocks: wnt[h][c][d]
    wnt_kernel<<<dim3(KVLORA / 32, QK_NOPE / 32, NH), dim3(32, 8)>>>(wkv_b_w, wnt);

    // 1) qa = x @ wq_a_w^T + b
    mma_gemm<<<dim3(12, 32, 1), blk>>>(qa, x, wq_a_w, wq_a_b, 1.f, 0,
        NTOK, QLORA, DIMX, DIMX, DIMX, QLORA, id, id, id);

    // 2) rmsnorm(qa)
    rmsnorm_kernel<<<NTOK, 256>>>(qa, q_norm_w, QLORA);

    // 3) q = qa @ wq_b_w^T + b
    mma_gemm<<<dim3(24, 32, 1), blk>>>(q, qa, wq_b_w, wq_b_b, 1.f, 0,
        NTOK, NH * QK_HEAD, QLORA, QLORA, QLORA, NH * QK_HEAD, id, id, id);

    // 4) kv = x @ wkv_a_w^T + b
    mma_gemm<<<dim3(5, 32, 1), blk>>>(kv, x, wkv_a_w, wkv_a_b, 1.f, 0,
        NTOK, KEFF, DIMX, DIMX, DIMX, KEFF, id, id, id);

    // 5) kvc = rmsnorm(kv[:,:512]); k_pe = rope(kv[:,512:])
    kv_post_kernel<<<NTOK, 256>>>(kv, kv_norm_w, freqs);

    // 5b) kvt[b][c][t] = kvc^T
    kvt_kernel<<<dim3(SEQ / 32, KVLORA / 32, BSZ), dim3(32, 8)>>>(kv, kvt);

    // 6) qeff[...,512:576] = rope(q_pe)
    qrope_kernel<<<NTOK, 512>>>(q, qeff, freqs);

    // 7) qeff[z,:, :512] = q_nope @ wnt[h]^T    (TN: B = wnt[h] [512,128])
    {
        BMap am = {NH, (long long)SEQ * NH * QK_HEAD, NH, QK_HEAD};
        BMap bm = {1, 0, NH, (long long)KVLORA * QK_NOPE};
        BMap cm = {1, (long long)SEQ * KEFF, 1, 0};
        mma_gemm<<<dim3(4, 16, 32), blk>>>(qeff, q, wnt, nullptr, 1.f, 0,
            SEQ, KVLORA, QK_NOPE, NH * QK_HEAD, QK_NOPE, KEFF, am, bm, cm);
    }

    // 8) scores = scale * Qeff @ Keff^T, causal (TN: B = kv rows [t,576])
    {
        BMap am = {1, (long long)SEQ * KEFF, 1, 0};
        BMap bm = {NH, (long long)SEQ * KEFF, 1, 0};
        BMap cm = {1, (long long)SEQ * SEQ, 1, 0};
        const float scale = 0.07216878364870323f;    // 192^-0.5
        mma_gemm<<<dim3(16, 16, 32), blk>>>(scr, qeff, kv, nullptr, scale, 1,
            SEQ, SEQ, KEFF, KEFF, KEFF, SEQ, am, bm, cm);
    }

    // 9) causal softmax rows
    softmax_kernel<<<BSZ * NH * SEQ, 256>>>(scr);

    // 10) ao = attn @ kvc   (TN: B = kvt[b] [512, 2048], k-limited)
    {
        BMap am = {1, (long long)SEQ * SEQ, 1, 0};
        BMap bm = {NH, (long long)KVLORA * SEQ, 1, 0};
        BMap cm = {1, (long long)SEQ * KVLORA, 1, 0};
        mma_gemm<<<dim3(4, 16, 32), blk>>>(ao, scr, kvt, nullptr, 1.f, 2,
            SEQ, KVLORA, SEQ, SEQ, SEQ, KVLORA, am, bm, cm);
    }

    // 11) ov = ao @ wv^T  (TN: B = wkv_b[h][128:256,:] rows [d,512])
    {
        BMap am = {1, (long long)SEQ * KVLORA, 1, 0};
        BMap bm = {1, 0, NH, (long long)256 * KVLORA};
        BMap cm = {NH, (long long)SEQ * NH * V_HEAD, NH, V_HEAD};
        mma_gemm<<<dim3(1, 16, 32), blk>>>(ov, ao, wkv_b_w + (long long)QK_NOPE * KVLORA,
            nullptr, 1.f, 0,
            SEQ, V_HEAD, KVLORA, KVLORA, KVLORA, NH * V_HEAD, am, bm, cm);
    }

    // 12) out = ov @ wo_w^T + wo_b
    mma_gemm<<<dim3(16, 32, 1), blk>>>(out, ov, wo_w, wo_b, 1.f, 0,
        NTOK, DIMX, NH * V_HEAD, NH * V_HEAD, NH * V_HEAD, DIMX, id, id, id);
}

// round 13
// speedup vs baseline: 1.2495x; 1.0004x over previous
#include <cuda_runtime.h>
#include <cuda_bf16.h>
#include <math.h>
#include <stdint.h>

// ---------------- problem constants ----------------
#define DIMX   2048
#define NH     16
#define QLORA  1536
#define KVLORA 512
#define ROPE_D 64
#define QK_NOPE 128
#define QK_HEAD 192     // 128 + 64
#define V_HEAD 128
#define BSZ    2
#define SEQ    2048
#define NTOK   (BSZ*SEQ)        // 4096
#define KEFF   (KVLORA+ROPE_D)  // 576
#define EPSF   1e-6f

#define NEG_INF __int_as_float(0xff800000)

// ---------------- scratch (static device arrays; no cudaMalloc allowed) ----
__device__ float g_qa  [(size_t)NTOK * QLORA];
__device__ float g_q   [(size_t)NTOK * NH * QK_HEAD];
__device__ float g_kv  [(size_t)NTOK * KEFF];             // kvc 512 | k_pe 64
__device__ float g_qeff[(size_t)BSZ * NH * SEQ * KEFF];   // absorbed q 512 | roped q_pe 64
__device__ float g_scr [(size_t)BSZ * NH * SEQ * SEQ];    // scores / attn
__device__ float g_ao  [(size_t)BSZ * NH * SEQ * KVLORA];
__device__ float g_ov  [(size_t)NTOK * NH * V_HEAD];
__device__ float g_wnt [(size_t)NH * KVLORA * QK_NOPE];   // wkv_b_nope^T per head [c][d]
__device__ float g_kvt [(size_t)BSZ * KVLORA * SEQ];      // kvc^T per batch [c][t]

// ---------------- batch offset map: off = (z/div)*s1 + (z%mod)*s2 ----------
struct BMap { int div; long long s1; int mod; long long s2; };
__device__ __forceinline__ long long boff(const BMap m, int z) {
    return (long long)(z / m.div) * m.s1 + (long long)(z % m.mod) * m.s2;
}

// ---------------- helpers ----------------
__device__ __forceinline__ uint32_t smem_u32(const void* p) {
    uint32_t a;
    asm("{ .reg .u64 t; cvta.to.shared.u64 t, %1; cvt.u32.u64 %0, t; }" : "=r"(a) : "l"(p));
    return a;
}
// v = hi + lo with hi, lo bf16; pack pairs (even k in low half)
__device__ __forceinline__ void split2(float x, float y, uint32_t& hi, uint32_t& lo) {
    __nv_bfloat16 hx = __float2bfloat16_rn(x);
    __nv_bfloat16 hy = __float2bfloat16_rn(y);
    __nv_bfloat16 lx = __float2bfloat16_rn(x - __bfloat162float(hx));
    __nv_bfloat16 ly = __float2bfloat16_rn(y - __bfloat162float(hy));
    hi = (uint32_t)__bfloat16_as_ushort(hx) | ((uint32_t)__bfloat16_as_ushort(hy) << 16);
    lo = (uint32_t)__bfloat16_as_ushort(lx) | ((uint32_t)__bfloat16_as_ushort(ly) << 16);
}

// mma.sync m16n8k16 bf16, fp32 accumulate
#define MMABF(d, a, b) \
    asm volatile("mma.sync.aligned.m16n8k16.row.col.f32.bf16.bf16.f32 " \
        "{%0,%1,%2,%3}, {%4,%5,%6,%7}, {%8,%9}, {%0,%1,%2,%3};" \
        : "+f"((d)[0]), "+f"((d)[1]), "+f"((d)[2]), "+f"((d)[3]) \
        : "r"((a)[0]), "r"((a)[1]), "r"((a)[2]), "r"((a)[3]), \
          "r"((b)[0]), "r"((b)[1]))

#define LDM_X4(r0, r1, r2, r3, addr) \
    asm volatile("ldmatrix.sync.aligned.m8n8.x4.shared.b16 {%0,%1,%2,%3}, [%4];" \
        : "=r"(r0), "=r"(r1), "=r"(r2), "=r"(r3) : "r"(addr))

// ---------------- split-bf16 batched TN GEMM (near-fp32 precision) ---------
// C[m,n] = alpha * sum_k A[m,k] * B[n,k]  (+bias[n])
// A: [M,K] lda;  B: [N,K] ldb; fp32 K-major.
// Requirements: M % 128 == 0, K % 16 == 0, N % 2 == 0.
// trik: 0 = none, 1 = causal (skip tiles with n0 >= m0+128; softmax masks rest),
//       2 = k-limit (A[m,k]==0 for k>m => Kend = m0+128)
#define GBM 128
#define GBN 128
#define GBK 16
#define PBW 12          // smem words per 16-elem bf16 row (24 bf16 = 16 + 8 pad)
#define PLW (GBM*PBW)   // words per plane (1536)

__global__ void __launch_bounds__(256)
mma_gemm(float* __restrict__ Cb, const float* __restrict__ Ab,
         const float* __restrict__ Bb, const float* __restrict__ bias,
         float alpha, int trik, int M, int N, int K,
         int lda, int ldb, int ldc, BMap am, BMap bm, BMap cm)
{
    const int z = blockIdx.z;
    const int m0 = blockIdx.y * GBM;
    const int n0 = blockIdx.x * GBN;
    if (trik == 1 && n0 >= m0 + GBM) return;   // fully masked tile

    // [buf][plane][row*PBW + word]
    __shared__ uint32_t sA[2][2][PLW];
    __shared__ uint32_t sB[2][2][PLW];

    const float* A = Ab + boff(am, z);
    const float* B = Bb + boff(bm, z);
    float*       C = Cb + boff(cm, z);

    const int tid  = threadIdx.x;
    const int wid  = tid >> 5;
    const int lane = tid & 31;
    const int wm   = wid & 1;          // 2 warps in m
    const int wn   = wid >> 1;         // 4 warps in n
    const int g    = lane >> 2;        // group id (0..7)
    const int c    = lane & 3;         // thread in group (0..3)

    int Kend = K;
    if (trik == 2) { int lim = m0 + GBM; Kend = (lim < K) ? lim : K; }

    float acc[4][4][4];
    #pragma unroll
    for (int i = 0; i < 4; i++)
        #pragma unroll
        for (int j = 0; j < 4; j++)
            #pragma unroll
            for (int l = 0; l < 4; l++) acc[i][j][l] = 0.f;

    // ---- ldmatrix per-thread base addresses (bytes) ----
    // A: row = wm*64 + mt*16 + (lane&15), koff = (lane>>4)*4 words
    const uint32_t sA0 = smem_u32(&sA[0][0][0]);
    const uint32_t sB0 = smem_u32(&sB[0][0][0]);
    const uint32_t aAddr0 = sA0 + (((wm * 64 + (lane & 15)) * PBW + (lane >> 4) * 4) << 2);
    // B: row = wn*32 + pair*16 + (lane&7) + ((lane>>4)<<3), koff = ((lane>>3)&1)*4
    const uint32_t bAddr0 = sB0 + (((wn * 32 + (lane & 7) + ((lane >> 4) << 3)) * PBW
                                    + ((lane >> 3) & 1) * 4) << 2);

    // per-thread store slots: chunks tid and tid+256 of 512 (row = chunk>>2, q = chunk&3)
    float4 ra[2], rb[2];
    const int row_[2] = { tid >> 2, (tid + 256) >> 2 };
    const int q_[2]   = { tid & 3, (tid + 256) & 3 };

    auto prefetch = [&](int k0) {
        #pragma unroll
        for (int i = 0; i < 2; i++) {
            int row = row_[i], q = q_[i];
            ra[i] = *reinterpret_cast<const float4*>(&A[(size_t)(m0 + row) * lda + k0 + q * 4]);
            if (n0 + row < N)
                rb[i] = *reinterpret_cast<const float4*>(&B[(size_t)(n0 + row) * ldb + k0 + q * 4]);
            else
                rb[i] = make_float4(0.f, 0.f, 0.f, 0.f);
        }
    };
    auto stores = [&](int buf) {
        #pragma unroll
        for (int i = 0; i < 2; i++) {
            int w = row_[i] * PBW + q_[i] * 2;
            uint32_t h0, l0, h1, l1;
            split2(ra[i].x, ra[i].y, h0, l0);
            split2(ra[i].z, ra[i].w, h1, l1);
            sA[buf][0][w] = h0; sA[buf][0][w + 1] = h1;
            sA[buf][1][w] = l0; sA[buf][1][w + 1] = l1;
            split2(rb[i].x, rb[i].y, h0, l0);
            split2(rb[i].z, rb[i].w, h1, l1);
            sB[buf][0][w] = h0; sB[buf][0][w + 1] = h1;
            sB[buf][1][w] = l0; sB[buf][1][w + 1] = l1;
        }
    };

    prefetch(0);
    stores(0);
    __syncthreads();

    int buf = 0;
    for (int k0 = 0; k0 < Kend; k0 += GBK) {
        const bool last = (k0 + GBK >= Kend);
        if (!last) prefetch(k0 + GBK);

        // fragment loads via ldmatrix (buf offset in bytes: buf*2*PLW*4)
        const uint32_t bufA = aAddr0 + (uint32_t)(buf * 2 * PLW) * 4u;
        const uint32_t bufB = bAddr0 + (uint32_t)(buf * 2 * PLW) * 4u;
        uint32_t ah[4][4], al[4][4], bh[4][2], bl[4][2];
        #pragma unroll
        for (int mt = 0; mt < 4; mt++) {
            uint32_t a = bufA + (uint32_t)(mt * 16 * PBW) * 4u;
            LDM_X4(ah[mt][0], ah[mt][1], ah[mt][2], ah[mt][3], a);
            LDM_X4(al[mt][0], al[mt][1], al[mt][2], al[mt][3], a + PLW * 4u);
        }
        #pragma unroll
        for (int pr = 0; pr < 2; pr++) {
            uint32_t b = bufB + (uint32_t)(pr * 16 * PBW) * 4u;
            LDM_X4(bh[2 * pr][0], bh[2 * pr][1], bh[2 * pr + 1][0], bh[2 * pr + 1][1], b);
            LDM_X4(bl[2 * pr][0], bl[2 * pr][1], bl[2 * pr + 1][0], bl[2 * pr + 1][1], b + PLW * 4u);
        }

        // pass 1: hi*hi; pass 2: hi*lo; pass 3: lo*hi (16-MMA dependency distance)
        #pragma unroll
        for (int mt = 0; mt < 4; mt++)
            #pragma unroll
            for (int nt = 0; nt < 4; nt++)
                MMABF(acc[mt][nt], ah[mt], bh[nt]);
        #pragma unroll
        for (int mt = 0; mt < 4; mt++)
            #pragma unroll
            for (int nt = 0; nt < 4; nt++)
                MMABF(acc[mt][nt], ah[mt], bl[nt]);
        #pragma unroll
        for (int mt = 0; mt < 4; mt++)
            #pragma unroll
            for (int nt = 0; nt < 4; nt++)
                MMABF(acc[mt][nt], al[mt], bh[nt]);

        if (!last) stores(buf ^ 1);
        __syncthreads();
        buf ^= 1;
    }

    // epilogue
    #pragma unroll
    for (int mt = 0; mt < 4; mt++) {
        int m = m0 + wm * 64 + mt * 16 + g;
        #pragma unroll
        for (int nt = 0; nt < 4; nt++) {
            int n = n0 + wn * 32 + nt * 8 + 2 * c;
            if (n >= N) continue;
            float b0 = 0.f, b1 = 0.f;
            if (bias) { b0 = bias[n]; b1 = bias[n + 1]; }
            float2 v0, v1;
            v0.x = acc[mt][nt][0] * alpha + b0;
            v0.y = acc[mt][nt][1] * alpha + b1;
            v1.x = acc[mt][nt][2] * alpha + b0;
            v1.y = acc[mt][nt][3] * alpha + b1;
            *reinterpret_cast<float2*>(&C[(size_t)m * ldc + n]) = v0;
            *reinterpret_cast<float2*>(&C[(size_t)(m + 8) * ldc + n]) = v1;
        }
    }
}

// ---------------- transposes ----------------
// wnt[h][c][d] = wkv_b[h][d][c]   (d < 128, c < 512; wkv_b row block = 256 rows)
__global__ void wnt_kernel(const float* __restrict__ w, float* __restrict__ wt) {
    __shared__ float t[32][33];
    int h = blockIdx.z;
    int c0 = blockIdx.x * 32, d0 = blockIdx.y * 32;
    int tx = threadIdx.x, ty = threadIdx.y;
    const float* src = w + (size_t)h * 256 * KVLORA;
    #pragma unroll
    for (int i = 0; i < 32; i += 8)
        t[ty + i][tx] = src[(size_t)(d0 + ty + i) * KVLORA + c0 + tx];
    __syncthreads();
    float* dst = wt + (size_t)h * KVLORA * QK_NOPE;
    #pragma unroll
    for (int i = 0; i < 32; i += 8)
        dst[(size_t)(c0 + ty + i) * QK_NOPE + d0 + tx] = t[tx][ty + i];
}

// kvt[b][c][t] = kv[b*SEQ + t][c]   (c < 512)
__global__ void kvt_kernel(const float* __restrict__ kv, float* __restrict__ kvt) {
    __shared__ float t[32][33];
    int b = blockIdx.z;
    int t0 = blockIdx.x * 32, c0 = blockIdx.y * 32;
    int tx = threadIdx.x, ty = threadIdx.y;
    const float* src = kv + (size_t)b * SEQ * KEFF;
    #pragma unroll
    for (int i = 0; i < 32; i += 8)
        t[ty + i][tx] = src[(size_t)(t0 + ty + i) * KEFF + c0 + tx];
    __syncthreads();
    float* dst = kvt + (size_t)b * KVLORA * SEQ;
    #pragma unroll
    for (int i = 0; i < 32; i += 8)
        dst[(size_t)(c0 + ty + i) * SEQ + t0 + tx] = t[tx][ty + i];
}

// ---------------- block reductions ----------------
__device__ __forceinline__ float block_reduce_sum(float v) {
    __shared__ float sh[32];
    int lane = threadIdx.x & 31, w = threadIdx.x >> 5;
    __syncthreads();
    #pragma unroll
    for (int o = 16; o; o >>= 1) v += __shfl_down_sync(0xffffffffu, v, o);
    if (lane == 0) sh[w] = v;
    __syncthreads();
    int nw = blockDim.x >> 5;
    v = (threadIdx.x < (unsigned)nw) ? sh[threadIdx.x] : 0.f;
    if (w == 0) {
        #pragma unroll
        for (int o = 16; o; o >>= 1) v += __shfl_down_sync(0xffffffffu, v, o);
        if (lane == 0) sh[0] = v;
    }
    __syncthreads();
    return sh[0];
}
__device__ __forceinline__ float block_reduce_max(float v) {
    __shared__ float sh[32];
    int lane = threadIdx.x & 31, w = threadIdx.x >> 5;
    __syncthreads();
    #pragma unroll
    for (int o = 16; o; o >>= 1) v = fmaxf(v, __shfl_down_sync(0xffffffffu, v, o));
    if (lane == 0) sh[w] = v;
    __syncthreads();
    int nw = blockDim.x >> 5;
    v = (threadIdx.x < (unsigned)nw) ? sh[threadIdx.x] : NEG_INF;
    if (w == 0) {
        #pragma unroll
        for (int o = 16; o; o >>= 1) v = fmaxf(v, __shfl_down_sync(0xffffffffu, v, o));
        if (lane == 0) sh[0] = v;
    }
    __syncthreads();
    return sh[0];
}

// ---------------- rmsnorm over a row of length n (in place) ----------------
__global__ void rmsnorm_kernel(float* __restrict__ x, const float* __restrict__ w, int n) {
    float* p = x + (long long)blockIdx.x * n;
    float ss = 0.f;
    for (int i = threadIdx.x; i < n; i += blockDim.x) { float v = p[i]; ss += v * v; }
    float tot = block_reduce_sum(ss);
    float scale = rsqrtf(tot / (float)n + EPSF);
    for (int i = threadIdx.x; i < n; i += blockDim.x) p[i] = p[i] * scale * w[i];
}

// ---------------- kv post: rmsnorm first 512, rope last 64 (in place) ------
__global__ void kv_post_kernel(float* __restrict__ kv, const float* __restrict__ w,
                               const float* __restrict__ freqs) {
    int t = blockIdx.x;
    int s = t % SEQ;
    float* p = kv + (long long)t * KEFF;
    float ss = 0.f;
    for (int i = threadIdx.x; i < KVLORA; i += blockDim.x) { float v = p[i]; ss += v * v; }
    float tot = block_reduce_sum(ss);
    float scale = rsqrtf(tot / (float)KVLORA + EPSF);
    for (int i = threadIdx.x; i < KVLORA; i += blockDim.x) p[i] = p[i] * scale * w[i];
    if (threadIdx.x < ROPE_D / 2) {
        int i = threadIdx.x;
        float c  = freqs[s * ROPE_D + 2 * i];
        float sn = freqs[s * ROPE_D + 2 * i + 1];
        float x0 = p[KVLORA + 2 * i], x1 = p[KVLORA + 2 * i + 1];
        p[KVLORA + 2 * i]     = x0 * c - x1 * sn;
        p[KVLORA + 2 * i + 1] = x1 * c + x0 * sn;
    }
}

// ---------------- rope q_pe -> qeff[..., 512:576] ----------------
__global__ void qrope_kernel(const float* __restrict__ q, float* __restrict__ qeff,
                             const float* __restrict__ freqs) {
    int t = blockIdx.x;
    int b = t / SEQ, s = t % SEQ;
    int h = threadIdx.x >> 5;
    int i = threadIdx.x & 31;
    float c  = freqs[s * ROPE_D + 2 * i];
    float sn = freqs[s * ROPE_D + 2 * i + 1];
    const float* qp = q + (long long)t * NH * QK_HEAD + h * QK_HEAD + QK_NOPE;
    float x0 = qp[2 * i], x1 = qp[2 * i + 1];
    float* o = qeff + ((long long)(b * NH + h) * SEQ + s) * KEFF + KVLORA;
    o[2 * i]     = x0 * c - x1 * sn;
    o[2 * i + 1] = x1 * c + x0 * sn;
}

// ---------------- causal row softmax (valid length s+1; zero above) --------
__global__ void softmax_kernel(float* __restrict__ S) {
    const int n = SEQ;
    int s = blockIdx.x % SEQ;       // row position within its (b,h) matrix
    float* p = S + (long long)blockIdx.x * n;
    float e[8];
    float mx = NEG_INF;
    #pragma unroll
    for (int k = 0; k < 8; k++) {
        int idx = threadIdx.x + k * 256;
        e[k] = (idx <= s) ? p[idx] : NEG_INF;
        mx = fmaxf(mx, e[k]);
    }
    mx = block_reduce_max(mx);
    float sum = 0.f;
    #pragma unroll
    for (int k = 0; k < 8; k++) {
        e[k] = expf(e[k] - mx);     // exp(-inf) = 0 for masked entries
        sum += e[k];
    }
    sum = block_reduce_sum(sum);
    float inv = 1.f / sum;
    #pragma unroll
    for (int k = 0; k < 8; k++) {
        int idx = threadIdx.x + k * 256;
        p[idx] = (idx <= s) ? e[k] * inv : 0.f;
    }
}

// ---------------- launch ----------------
extern "C" void kernel_launch(void* const* d_in, const int* in_sizes, int n_in,
                              void* d_out, int out_size) {
    int pbase = (n_in > 3 && in_sizes[3] == 1) ? 4 : 3;
    const float* x         = (const float*)d_in[0];
    const float* freqs     = (const float*)d_in[1];
    const float* wq_a_w    = (const float*)d_in[pbase + 0];
    const float* wq_a_b    = (const float*)d_in[pbase + 1];
    const float* q_norm_w  = (const float*)d_in[pbase + 2];
    const float* wq_b_w    = (const float*)d_in[pbase + 3];
    const float* wq_b_b    = (const float*)d_in[pbase + 4];
    const float* wkv_a_w   = (const float*)d_in[pbase + 5];
    const float* wkv_a_b   = (const float*)d_in[pbase + 6];
    const float* kv_norm_w = (const float*)d_in[pbase + 7];
    const float* wkv_b_w   = (const float*)d_in[pbase + 8];
    const float* wo_w      = (const float*)d_in[pbase + 9];
    const float* wo_b      = (const float*)d_in[pbase + 10];
    float* out = (float*)d_out;

    float *qa, *q, *kv, *qeff, *scr, *ao, *ov, *wnt, *kvt;
    cudaGetSymbolAddress((void**)&qa,   g_qa);
    cudaGetSymbolAddress((void**)&q,    g_q);
    cudaGetSymbolAddress((void**)&kv,   g_kv);
    cudaGetSymbolAddress((void**)&qeff, g_qeff);
    cudaGetSymbolAddress((void**)&scr,  g_scr);
    cudaGetSymbolAddress((void**)&ao,   g_ao);
    cudaGetSymbolAddress((void**)&ov,   g_ov);
    cudaGetSymbolAddress((void**)&wnt,  g_wnt);
    cudaGetSymbolAddress((void**)&kvt,  g_kvt);

    const BMap id = {1, 0, 1, 0};
    const dim3 blk(256);

    // 0) transpose wkv_b nope blocks: wnt[h][c][d]
    wnt_kernel<<<dim3(KVLORA / 32, QK_NOPE / 32, NH), dim3(32, 8)>>>(wkv_b_w, wnt);

    // 1) qa = x @ wq_a_w^T + b
    mma_gemm<<<dim3(12, 32, 1), blk>>>(qa, x, wq_a_w, wq_a_b, 1.f, 0,
        NTOK, QLORA, DIMX, DIMX, DIMX, QLORA, id, id, id);

    // 2) rmsnorm(qa)
    rmsnorm_kernel<<<NTOK, 256>>>(qa, q_norm_w, QLORA);

    // 3) q = qa @ wq_b_w^T + b
    mma_gemm<<<dim3(24, 32, 1), blk>>>(q, qa, wq_b_w, wq_b_b, 1.f, 0,
        NTOK, NH * QK_HEAD, QLORA, QLORA, QLORA, NH * QK_HEAD, id, id, id);

    // 4) kv = x @ wkv_a_w^T + b
    mma_gemm<<<dim3(5, 32, 1), blk>>>(kv, x, wkv_a_w, wkv_a_b, 1.f, 0,
        NTOK, KEFF, DIMX, DIMX, DIMX, KEFF, id, id, id);

    // 5) kvc = rmsnorm(kv[:,:512]); k_pe = rope(kv[:,512:])
    kv_post_kernel<<<NTOK, 256>>>(kv, kv_norm_w, freqs);

    // 5b) kvt[b][c][t] = kvc^T
    kvt_kernel<<<dim3(SEQ / 32, KVLORA / 32, BSZ), dim3(32, 8)>>>(kv, kvt);

    // 6) qeff[...,512:576] = rope(q_pe)
    qrope_kernel<<<NTOK, 512>>>(q, qeff, freqs);

    // 7) qeff[z,:, :512] = q_nope @ wnt[h]^T    (TN: B = wnt[h] [512,128])
    {
        BMap am = {NH, (long long)SEQ * NH * QK_HEAD, NH, QK_HEAD};
        BMap bm = {1, 0, NH, (long long)KVLORA * QK_NOPE};
        BMap cm = {1, (long long)SEQ * KEFF, 1, 0};
        mma_gemm<<<dim3(4, 16, 32), blk>>>(qeff, q, wnt, nullptr, 1.f, 0,
            SEQ, KVLORA, QK_NOPE, NH * QK_HEAD, QK_NOPE, KEFF, am, bm, cm);
    }

    // 8) scores = scale * Qeff @ Keff^T, causal (TN: B = kv rows [t,576])
    {
        BMap am = {1, (long long)SEQ * KEFF, 1, 0};
        BMap bm = {NH, (long long)SEQ * KEFF, 1, 0};
        BMap cm = {1, (long long)SEQ * SEQ, 1, 0};
        const float scale = 0.07216878364870323f;    // 192^-0.5
        mma_gemm<<<dim3(16, 16, 32), blk>>>(scr, qeff, kv, nullptr, scale, 1,
            SEQ, SEQ, KEFF, KEFF, KEFF, SEQ, am, bm, cm);
    }

    // 9) causal softmax rows
    softmax_kernel<<<BSZ * NH * SEQ, 256>>>(scr);

    // 10) ao = attn @ kvc   (TN: B = kvt[b] [512, 2048], k-limited)
    {
        BMap am = {1, (long long)SEQ * SEQ, 1, 0};
        BMap bm = {NH, (long long)KVLORA * SEQ, 1, 0};
        BMap cm = {1, (long long)SEQ * KVLORA, 1, 0};
        mma_gemm<<<dim3(4, 16, 32), blk>>>(ao, scr, kvt, nullptr, 1.f, 2,
            SEQ, KVLORA, SEQ, SEQ, SEQ, KVLORA, am, bm, cm);
    }

    // 11) ov = ao @ wv^T  (TN: B = wkv_b[h][128:256,:] rows [d,512])
    {
        BMap am = {1, (long long)SEQ * KVLORA, 1, 0};
        BMap bm = {1, 0, NH, (long long)256 * KVLORA};
        BMap cm = {NH, (long long)SEQ * NH * V_HEAD, NH, V_HEAD};
        mma_gemm<<<dim3(1, 16, 32), blk>>>(ov, ao, wkv_b_w + (long long)QK_NOPE * KVLORA,
            nullptr, 1.f, 0,
            SEQ, V_HEAD, KVLORA, KVLORA, KVLORA, NH * V_HEAD, am, bm, cm);
    }

    // 12) out = ov @ wo_w^T + wo_b
    mma_gemm<<<dim3(16, 32, 1), blk>>>(out, ov, wo_w, wo_b, 1.f, 0,
        NTOK, DIMX, NH * V_HEAD, NH * V_HEAD, NH * V_HEAD, DIMX, id, id, id);
}

// round 14
// speedup vs baseline: 1.2498x; 1.0003x over previous
#include <cuda_runtime.h>
#include <cuda_bf16.h>
#include <math.h>
#include <stdint.h>

// ---------------- problem constants ----------------
#define DIMX   2048
#define NH     16
#define QLORA  1536
#define KVLORA 512
#define ROPE_D 64
#define QK_NOPE 128
#define QK_HEAD 192     // 128 + 64
#define V_HEAD 128
#define BSZ    2
#define SEQ    2048
#define NTOK   (BSZ*SEQ)        // 4096
#define KEFF   (KVLORA+ROPE_D)  // 576
#define EPSF   1e-6f

#define NEG_INF __int_as_float(0xff800000)

// ---------------- scratch (static device arrays; no cudaMalloc allowed) ----
__device__ float g_qa  [(size_t)NTOK * QLORA];
__device__ float g_q   [(size_t)NTOK * NH * QK_HEAD];
__device__ float g_kv  [(size_t)NTOK * KEFF];             // kvc 512 | k_pe 64
__device__ float g_qeff[(size_t)BSZ * NH * SEQ * KEFF];   // absorbed q 512 | roped q_pe 64
__device__ float g_scr [(size_t)BSZ * NH * SEQ * SEQ];    // scores / attn
__device__ float g_ao  [(size_t)BSZ * NH * SEQ * KVLORA];
__device__ float g_ov  [(size_t)NTOK * NH * V_HEAD];
__device__ float g_wnt [(size_t)NH * KVLORA * QK_NOPE];   // wkv_b_nope^T per head [c][d]
__device__ float g_kvt [(size_t)BSZ * KVLORA * SEQ];      // kvc^T per batch [c][t]

// ---------------- batch offset map: off = (z/div)*s1 + (z%mod)*s2 ----------
struct BMap { int div; long long s1; int mod; long long s2; };
__device__ __forceinline__ long long boff(const BMap m, int z) {
    return (long long)(z / m.div) * m.s1 + (long long)(z % m.mod) * m.s2;
}

// ---------------- helpers ----------------
__device__ __forceinline__ uint32_t smem_u32(const void* p) {
    uint32_t a;
    asm("{ .reg .u64 t; cvta.to.shared.u64 t, %1; cvt.u32.u64 %0, t; }" : "=r"(a) : "l"(p));
    return a;
}
// v = hi + lo with hi, lo bf16; pack pairs (even k in low half)
__device__ __forceinline__ void split2(float x, float y, uint32_t& hi, uint32_t& lo) {
    __nv_bfloat16 hx = __float2bfloat16_rn(x);
    __nv_bfloat16 hy = __float2bfloat16_rn(y);
    __nv_bfloat16 lx = __float2bfloat16_rn(x - __bfloat162float(hx));
    __nv_bfloat16 ly = __float2bfloat16_rn(y - __bfloat162float(hy));
    hi = (uint32_t)__bfloat16_as_ushort(hx) | ((uint32_t)__bfloat16_as_ushort(hy) << 16);
    lo = (uint32_t)__bfloat16_as_ushort(lx) | ((uint32_t)__bfloat16_as_ushort(ly) << 16);
}

// mma.sync m16n8k16 bf16, fp32 accumulate
#define MMABF(d, a, b) \
    asm volatile("mma.sync.aligned.m16n8k16.row.col.f32.bf16.bf16.f32 " \
        "{%0,%1,%2,%3}, {%4,%5,%6,%7}, {%8,%9}, {%0,%1,%2,%3};" \
        : "+f"((d)[0]), "+f"((d)[1]), "+f"((d)[2]), "+f"((d)[3]) \
        : "r"((a)[0]), "r"((a)[1]), "r"((a)[2]), "r"((a)[3]), \
          "r"((b)[0]), "r"((b)[1]))

#define LDM_X4(r0, r1, r2, r3, addr) \
    asm volatile("ldmatrix.sync.aligned.m8n8.x4.shared.b16 {%0,%1,%2,%3}, [%4];" \
        : "=r"(r0), "=r"(r1), "=r"(r2), "=r"(r3) : "r"(addr))

// ---------------- split-bf16 batched TN GEMM (near-fp32 precision) ---------
// C[m,n] = alpha * sum_k A[m,k] * B[n,k]  (+bias[n])
// A: [M,K] lda;  B: [N,K] ldb; fp32 K-major.
// Requirements: M % 128 == 0, K % 16 == 0, N % 2 == 0.
// trik: 0 = none, 1 = causal (skip tiles with n0 >= m0+128; softmax masks rest),
//       2 = k-limit (A[m,k]==0 for k>m => Kend = m0+128)
#define GBM 128
#define GBN 128
#define GBK 16
#define PBW 12          // smem words per 16-elem bf16 row (24 bf16 = 16 + 8 pad)
#define PLW (GBM*PBW)   // words per plane (1536)

__global__ void __launch_bounds__(256)
mma_gemm(float* __restrict__ Cb, const float* __restrict__ Ab,
         const float* __restrict__ Bb, const float* __restrict__ bias,
         float alpha, int trik, int M, int N, int K,
         int lda, int ldb, int ldc, BMap am, BMap bm, BMap cm)
{
    const int z = blockIdx.z;
    const int m0 = blockIdx.y * GBM;
    const int n0 = blockIdx.x * GBN;
    if (trik == 1 && n0 >= m0 + GBM) return;   // fully masked tile

    // [buf][plane][row*PBW + word]
    __shared__ uint32_t sA[2][2][PLW];
    __shared__ uint32_t sB[2][2][PLW];

    const float* A = Ab + boff(am, z);
    const float* B = Bb + boff(bm, z);
    float*       C = Cb + boff(cm, z);

    const int tid  = threadIdx.x;
    const int wid  = tid >> 5;
    const int lane = tid & 31;
    const int wm   = wid & 1;          // 2 warps in m
    const int wn   = wid >> 1;         // 4 warps in n
    const int g    = lane >> 2;        // group id (0..7)
    const int c    = lane & 3;         // thread in group (0..3)

    int Kend = K;
    if (trik == 2) { int lim = m0 + GBM; Kend = (lim < K) ? lim : K; }

    float acc[4][4][4];
    #pragma unroll
    for (int i = 0; i < 4; i++)
        #pragma unroll
        for (int j = 0; j < 4; j++)
            #pragma unroll
            for (int l = 0; l < 4; l++) acc[i][j][l] = 0.f;

    // ---- ldmatrix per-thread base addresses (bytes) ----
    // A: row = wm*64 + mt*16 + (lane&15), koff = (lane>>4)*4 words
    const uint32_t sA0 = smem_u32(&sA[0][0][0]);
    const uint32_t sB0 = smem_u32(&sB[0][0][0]);
    const uint32_t aAddr0 = sA0 + (((wm * 64 + (lane & 15)) * PBW + (lane >> 4) * 4) << 2);
    // B: row = wn*32 + pair*16 + (lane&7) + ((lane>>4)<<3), koff = ((lane>>3)&1)*4
    const uint32_t bAddr0 = sB0 + (((wn * 32 + (lane & 7) + ((lane >> 4) << 3)) * PBW
                                    + ((lane >> 3) & 1) * 4) << 2);

    // per-thread store slots: chunks tid and tid+256 of 512 (row = chunk>>2, q = chunk&3)
    float4 ra[2], rb[2];
    const int row_[2] = { tid >> 2, (tid + 256) >> 2 };
    const int q_[2]   = { tid & 3, (tid + 256) & 3 };

    auto prefetch = [&](int k0) {
        #pragma unroll
        for (int i = 0; i < 2; i++) {
            int row = row_[i], q = q_[i];
            ra[i] = *reinterpret_cast<const float4*>(&A[(size_t)(m0 + row) * lda + k0 + q * 4]);
            if (n0 + row < N)
                rb[i] = *reinterpret_cast<const float4*>(&B[(size_t)(n0 + row) * ldb + k0 + q * 4]);
            else
                rb[i] = make_float4(0.f, 0.f, 0.f, 0.f);
        }
    };
    auto stores = [&](int buf) {
        #pragma unroll
        for (int i = 0; i < 2; i++) {
            int w = row_[i] * PBW + q_[i] * 2;
            uint32_t h0, l0, h1, l1;
            split2(ra[i].x, ra[i].y, h0, l0);
            split2(ra[i].z, ra[i].w, h1, l1);
            sA[buf][0][w] = h0; sA[buf][0][w + 1] = h1;
            sA[buf][1][w] = l0; sA[buf][1][w + 1] = l1;
            split2(rb[i].x, rb[i].y, h0, l0);
            split2(rb[i].z, rb[i].w, h1, l1);
            sB[buf][0][w] = h0; sB[buf][0][w + 1] = h1;
            sB[buf][1][w] = l0; sB[buf][1][w + 1] = l1;
        }
    };

    prefetch(0);
    stores(0);
    __syncthreads();

    int buf = 0;
    for (int k0 = 0; k0 < Kend; k0 += GBK) {
        const bool last = (k0 + GBK >= Kend);
        if (!last) prefetch(k0 + GBK);

        // fragment loads via ldmatrix (buf offset in bytes: buf*2*PLW*4)
        const uint32_t bufA = aAddr0 + (uint32_t)(buf * 2 * PLW) * 4u;
        const uint32_t bufB = bAddr0 + (uint32_t)(buf * 2 * PLW) * 4u;
        uint32_t ah[4][4], al[4][4], bh[4][2], bl[4][2];
        #pragma unroll
        for (int mt = 0; mt < 4; mt++) {
            uint32_t a = bufA + (uint32_t)(mt * 16 * PBW) * 4u;
            LDM_X4(ah[mt][0], ah[mt][1], ah[mt][2], ah[mt][3], a);
            LDM_X4(al[mt][0], al[mt][1], al[mt][2], al[mt][3], a + PLW * 4u);
        }
        #pragma unroll
        for (int pr = 0; pr < 2; pr++) {
            uint32_t b = bufB + (uint32_t)(pr * 16 * PBW) * 4u;
            LDM_X4(bh[2 * pr][0], bh[2 * pr][1], bh[2 * pr + 1][0], bh[2 * pr + 1][1], b);
            LDM_X4(bl[2 * pr][0], bl[2 * pr][1], bl[2 * pr + 1][0], bl[2 * pr + 1][1], b + PLW * 4u);
        }

        // pass 1: hi*hi; pass 2: hi*lo; pass 3: lo*hi (16-MMA dependency distance)
        #pragma unroll
        for (int mt = 0; mt < 4; mt++)
            #pragma unroll
            for (int nt = 0; nt < 4; nt++)
                MMABF(acc[mt][nt], ah[mt], bh[nt]);
        #pragma unroll
        for (int mt = 0; mt < 4; mt++)
            #pragma unroll
            for (int nt = 0; nt < 4; nt++)
                MMABF(acc[mt][nt], ah[mt], bl[nt]);
        #pragma unroll
        for (int mt = 0; mt < 4; mt++)
            #pragma unroll
            for (int nt = 0; nt < 4; nt++)
                MMABF(acc[mt][nt], al[mt], bh[nt]);

        if (!last) stores(buf ^ 1);
        __syncthreads();
        buf ^= 1;
    }

    // epilogue
    #pragma unroll
    for (int mt = 0; mt < 4; mt++) {
        int m = m0 + wm * 64 + mt * 16 + g;
        #pragma unroll
        for (int nt = 0; nt < 4; nt++) {
            int n = n0 + wn * 32 + nt * 8 + 2 * c;
            if (n >= N) continue;
            float b0 = 0.f, b1 = 0.f;
            if (bias) { b0 = bias[n]; b1 = bias[n + 1]; }
            float2 v0, v1;
            v0.x = acc[mt][nt][0] * alpha + b0;
            v0.y = acc[mt][nt][1] * alpha + b1;
            v1.x = acc[mt][nt][2] * alpha + b0;
            v1.y = acc[mt][nt][3] * alpha + b1;
            *reinterpret_cast<float2*>(&C[(size_t)m * ldc + n]) = v0;
            *reinterpret_cast<float2*>(&C[(size_t)(m + 8) * ldc + n]) = v1;
        }
    }
}

// ---------------- transposes ----------------
// wnt[h][c][d] = wkv_b[h][d][c]   (d < 128, c < 512; wkv_b row block = 256 rows)
__global__ void wnt_kernel(const float* __restrict__ w, float* __restrict__ wt) {
    __shared__ float t[32][33];
    int h = blockIdx.z;
    int c0 = blockIdx.x * 32, d0 = blockIdx.y * 32;
    int tx = threadIdx.x, ty = threadIdx.y;
    const float* src = w + (size_t)h * 256 * KVLORA;
    #pragma unroll
    for (int i = 0; i < 32; i += 8)
        t[ty + i][tx] = src[(size_t)(d0 + ty + i) * KVLORA + c0 + tx];
    __syncthreads();
    float* dst = wt + (size_t)h * KVLORA * QK_NOPE;
    #pragma unroll
    for (int i = 0; i < 32; i += 8)
        dst[(size_t)(c0 + ty + i) * QK_NOPE + d0 + tx] = t[tx][ty + i];
}

// kvt[b][c][t] = kv[b*SEQ + t][c]   (c < 512)
__global__ void kvt_kernel(const float* __restrict__ kv, float* __restrict__ kvt) {
    __shared__ float t[32][33];
    int b = blockIdx.z;
    int t0 = blockIdx.x * 32, c0 = blockIdx.y * 32;
    int tx = threadIdx.x, ty = threadIdx.y;
    const float* src = kv + (size_t)b * SEQ * KEFF;
    #pragma unroll
    for (int i = 0; i < 32; i += 8)
        t[ty + i][tx] = src[(size_t)(t0 + ty + i) * KEFF + c0 + tx];
    __syncthreads();
    float* dst = kvt + (size_t)b * KVLORA * SEQ;
    #pragma unroll
    for (int i = 0; i < 32; i += 8)
        dst[(size_t)(c0 + ty + i) * SEQ + t0 + tx] = t[tx][ty + i];
}

// ---------------- block reductions ----------------
__device__ __forceinline__ float block_reduce_sum(float v) {
    __shared__ float sh[32];
    int lane = threadIdx.x & 31, w = threadIdx.x >> 5;
    __syncthreads();
    #pragma unroll
    for (int o = 16; o; o >>= 1) v += __shfl_down_sync(0xffffffffu, v, o);
    if (lane == 0) sh[w] = v;
    __syncthreads();
    int nw = blockDim.x >> 5;
    v = (threadIdx.x < (unsigned)nw) ? sh[threadIdx.x] : 0.f;
    if (w == 0) {
        #pragma unroll
        for (int o = 16; o; o >>= 1) v += __shfl_down_sync(0xffffffffu, v, o);
        if (lane == 0) sh[0] = v;
    }
    __syncthreads();
    return sh[0];
}
__device__ __forceinline__ float block_reduce_max(float v) {
    __shared__ float sh[32];
    int lane = threadIdx.x & 31, w = threadIdx.x >> 5;
    __syncthreads();
    #pragma unroll
    for (int o = 16; o; o >>= 1) v = fmaxf(v, __shfl_down_sync(0xffffffffu, v, o));
    if (lane == 0) sh[w] = v;
    __syncthreads();
    int nw = blockDim.x >> 5;
    v = (threadIdx.x < (unsigned)nw) ? sh[threadIdx.x] : NEG_INF;
    if (w == 0) {
        #pragma unroll
        for (int o = 16; o; o >>= 1) v = fmaxf(v, __shfl_down_sync(0xffffffffu, v, o));
        if (lane == 0) sh[0] = v;
    }
    __syncthreads();
    return sh[0];
}

// ---------------- rmsnorm over a row of length n (in place) ----------------
__global__ void rmsnorm_kernel(float* __restrict__ x, const float* __restrict__ w, int n) {
    float* p = x + (long long)blockIdx.x * n;
    float ss = 0.f;
    for (int i = threadIdx.x; i < n; i += blockDim.x) { float v = p[i]; ss += v * v; }
    float tot = block_reduce_sum(ss);
    float scale = rsqrtf(tot / (float)n + EPSF);
    for (int i = threadIdx.x; i < n; i += blockDim.x) p[i] = p[i] * scale * w[i];
}

// ---------------- kv post: rmsnorm first 512, rope last 64 (in place) ------
__global__ void kv_post_kernel(float* __restrict__ kv, const float* __restrict__ w,
                               const float* __restrict__ freqs) {
    int t = blockIdx.x;
    int s = t % SEQ;
    float* p = kv + (long long)t * KEFF;
    float ss = 0.f;
    for (int i = threadIdx.x; i < KVLORA; i += blockDim.x) { float v = p[i]; ss += v * v; }
    float tot = block_reduce_sum(ss);
    float scale = rsqrtf(tot / (float)KVLORA + EPSF);
    for (int i = threadIdx.x; i < KVLORA; i += blockDim.x) p[i] = p[i] * scale * w[i];
    if (threadIdx.x < ROPE_D / 2) {
        int i = threadIdx.x;
        float c  = freqs[s * ROPE_D + 2 * i];
        float sn = freqs[s * ROPE_D + 2 * i + 1];
        float x0 = p[KVLORA + 2 * i], x1 = p[KVLORA + 2 * i + 1];
        p[KVLORA + 2 * i]     = x0 * c - x1 * sn;
        p[KVLORA + 2 * i + 1] = x1 * c + x0 * sn;
    }
}

// ---------------- rope q_pe -> qeff[..., 512:576] ----------------
__global__ void qrope_kernel(const float* __restrict__ q, float* __restrict__ qeff,
                             const float* __restrict__ freqs) {
    int t = blockIdx.x;
    int b = t / SEQ, s = t % SEQ;
    int h = threadIdx.x >> 5;
    int i = threadIdx.x & 31;
    float c  = freqs[s * ROPE_D + 2 * i];
    float sn = freqs[s * ROPE_D + 2 * i + 1];
    const float* qp = q + (long long)t * NH * QK_HEAD + h * QK_HEAD + QK_NOPE;
    float x0 = qp[2 * i], x1 = qp[2 * i + 1];
    float* o = qeff + ((long long)(b * NH + h) * SEQ + s) * KEFF + KVLORA;
    o[2 * i]     = x0 * c - x1 * sn;
    o[2 * i + 1] = x1 * c + x0 * sn;
}

// ---------------- causal row softmax (valid length s+1; zero above) --------
__global__ void softmax_kernel(float* __restrict__ S) {
    const int n = SEQ;
    int s = blockIdx.x % SEQ;       // row position within its (b,h) matrix
    float* p = S + (long long)blockIdx.x * n;
    float e[8];
    float mx = NEG_INF;
    #pragma unroll
    for (int k = 0; k < 8; k++) {
        int idx = threadIdx.x + k * 256;
        e[k] = (idx <= s) ? p[idx] : NEG_INF;
        mx = fmaxf(mx, e[k]);
    }
    mx = block_reduce_max(mx);
    float sum = 0.f;
    #pragma unroll
    for (int k = 0; k < 8; k++) {
        e[k] = expf(e[k] - mx);     // exp(-inf) = 0 for masked entries
        sum += e[k];
    }
    sum = block_reduce_sum(sum);
    float inv = 1.f / sum;
    #pragma unroll
    for (int k = 0; k < 8; k++) {
        int idx = threadIdx.x + k * 256;
        p[idx] = (idx <= s) ? e[k] * inv : 0.f;
    }
}

// ---------------- launch ----------------
extern "C" void kernel_launch(void* const* d_in, const int* in_sizes, int n_in,
                              void* d_out, int out_size) {
    int pbase = (n_in > 3 && in_sizes[3] == 1) ? 4 : 3;
    const float* x         = (const float*)d_in[0];
    const float* freqs     = (const float*)d_in[1];
    const float* wq_a_w    = (const float*)d_in[pbase + 0];
    const float* wq_a_b    = (const float*)d_in[pbase + 1];
    const float* q_norm_w  = (const float*)d_in[pbase + 2];
    const float* wq_b_w    = (const float*)d_in[pbase + 3];
    const float* wq_b_b    = (const float*)d_in[pbase + 4];
    const float* wkv_a_w   = (const float*)d_in[pbase + 5];
    const float* wkv_a_b   = (const float*)d_in[pbase + 6];
    const float* kv_norm_w = (const float*)d_in[pbase + 7];
    const float* wkv_b_w   = (const float*)d_in[pbase + 8];
    const float* wo_w      = (const float*)d_in[pbase + 9];
    const float* wo_b      = (const float*)d_in[pbase + 10];
    float* out = (float*)d_out;

    float *qa, *q, *kv, *qeff, *scr, *ao, *ov, *wnt, *kvt;
    cudaGetSymbolAddress((void**)&qa,   g_qa);
    cudaGetSymbolAddress((void**)&q,    g_q);
    cudaGetSymbolAddress((void**)&kv,   g_kv);
    cudaGetSymbolAddress((void**)&qeff, g_qeff);
    cudaGetSymbolAddress((void**)&scr,  g_scr);
    cudaGetSymbolAddress((void**)&ao,   g_ao);
    cudaGetSymbolAddress((void**)&ov,   g_ov);
    cudaGetSymbolAddress((void**)&wnt,  g_wnt);
    cudaGetSymbolAddress((void**)&kvt,  g_kvt);

    const BMap id = {1, 0, 1, 0};
    const dim3 blk(256);

    // 0) transpose wkv_b nope blocks: wnt[h][c][d]
    wnt_kernel<<<dim3(KVLORA / 32, QK_NOPE / 32, NH), dim3(32, 8)>>>(wkv_b_w, wnt);

    // 1) qa = x @ wq_a_w^T + b
    mma_gemm<<<dim3(12, 32, 1), blk>>>(qa, x, wq_a_w, wq_a_b, 1.f, 0,
        NTOK, QLORA, DIMX, DIMX, DIMX, QLORA, id, id, id);

    // 2) rmsnorm(qa)
    rmsnorm_kernel<<<NTOK, 256>>>(qa, q_norm_w, QLORA);

    // 3) q = qa @ wq_b_w^T + b
    mma_gemm<<<dim3(24, 32, 1), blk>>>(q, qa, wq_b_w, wq_b_b, 1.f, 0,
        NTOK, NH * QK_HEAD, QLORA, QLORA, QLORA, NH * QK_HEAD, id, id, id);

    // 4) kv = x @ wkv_a_w^T + b
    mma_gemm<<<dim3(5, 32, 1), blk>>>(kv, x, wkv_a_w, wkv_a_b, 1.f, 0,
        NTOK, KEFF, DIMX, DIMX, DIMX, KEFF, id, id, id);

    // 5) kvc = rmsnorm(kv[:,:512]); k_pe = rope(kv[:,512:])
    kv_post_kernel<<<NTOK, 256>>>(kv, kv_norm_w, freqs);

    // 5b) kvt[b][c][t] = kvc^T
    kvt_kernel<<<dim3(SEQ / 32, KVLORA / 32, BSZ), dim3(32, 8)>>>(kv, kvt);

    // 6) qeff[...,512:576] = rope(q_pe)
    qrope_kernel<<<NTOK, 512>>>(q, qeff, freqs);

    // 7) qeff[z,:, :512] = q_nope @ wnt[h]^T    (TN: B = wnt[h] [512,128])
    {
        BMap am = {NH, (long long)SEQ * NH * QK_HEAD, NH, QK_HEAD};
        BMap bm = {1, 0, NH, (long long)KVLORA * QK_NOPE};
        BMap cm = {1, (long long)SEQ * KEFF, 1, 0};
        mma_gemm<<<dim3(4, 16, 32), blk>>>(qeff, q, wnt, nullptr, 1.f, 0,
            SEQ, KVLORA, QK_NOPE, NH * QK_HEAD, QK_NOPE, KEFF, am, bm, cm);
    }

    // 8) scores = scale * Qeff @ Keff^T, causal (TN: B = kv rows [t,576])
    {
        BMap am = {1, (long long)SEQ * KEFF, 1, 0};
        BMap bm = {NH, (long long)SEQ * KEFF, 1, 0};
        BMap cm = {1, (long long)SEQ * SEQ, 1, 0};
        const float scale = 0.07216878364870323f;    // 192^-0.5
        mma_gemm<<<dim3(16, 16, 32), blk>>>(scr, qeff, kv, nullptr, scale, 1,
            SEQ, SEQ, KEFF, KEFF, KEFF, SEQ, am, bm, cm);
    }

    // 9) causal softmax rows
    softmax_kernel<<<BSZ * NH * SEQ, 256>>>(scr);

    // 10) ao = attn @ kvc   (TN: B = kvt[b] [512, 2048], k-limited)
    {
        BMap am = {1, (long long)SEQ * SEQ, 1, 0};
        BMap bm = {NH, (long long)KVLORA * SEQ, 1, 0};
        BMap cm = {1, (long long)SEQ * KVLORA, 1, 0};
        mma_gemm<<<dim3(4, 16, 32), blk>>>(ao, scr, kvt, nullptr, 1.f, 2,
            SEQ, KVLORA, SEQ, SEQ, SEQ, KVLORA, am, bm, cm);
    }

    // 11) ov = ao @ wv^T  (TN: B = wkv_b[h][128:256,:] rows [d,512])
    {
        BMap am = {1, (long long)SEQ * KVLORA, 1, 0};
        BMap bm = {1, 0, NH, (long long)256 * KVLORA};
        BMap cm = {NH, (long long)SEQ * NH * V_HEAD, NH, V_HEAD};
        mma_gemm<<<dim3(1, 16, 32), blk>>>(ov, ao, wkv_b_w + (long long)QK_NOPE * KVLORA,
            nullptr, 1.f, 0,
            SEQ, V_HEAD, KVLORA, KVLORA, KVLORA, NH * V_HEAD, am, bm, cm);
    }

    // 12) out = ov @ wo_w^T + wo_b
    mma_gemm<<<dim3(16, 32, 1), blk>>>(out, ov, wo_w, wo_b, 1.f, 0,
        NTOK, DIMX, NH * V_HEAD, NH * V_HEAD, NH * V_HEAD, DIMX, id, id, id);
}